// round 1
// baseline (speedup 1.0000x reference)
#include <cuda_runtime.h>

#define Pn    784
#define BATCH 16
#define CIN   512
#define CMID  128
#define CRED  32
#define NG    8
#define KK    49
#define CSPAN 392   // KK * NG

// Scratch (device globals: allocation-free rule)
__device__ float g_out1[BATCH * CMID * Pn];   // 6.4 MB
__device__ float g_w[BATCH * CSPAN * Pn];     // 19.7 MB
__device__ float g_out2[BATCH * CMID * Pn];   // 6.4 MB

// ---------------------------------------------------------------------------
// Kernel 1: conv1 1x1 (512->128) + BN + ReLU.  C[128, px] = W1[128,512] @ X
// grid (7 px-tiles, 16 batch), 256 threads, 8x8 microtile, BK=8
// ---------------------------------------------------------------------------
__global__ __launch_bounds__(256) void k_conv1(const float* __restrict__ x,
                                               const float* __restrict__ W1,
                                               const float* __restrict__ s1,
                                               const float* __restrict__ b1) {
    __shared__ float As[8][132];
    __shared__ float Bs[8][128];
    const int b   = blockIdx.y;
    const int n0  = blockIdx.x * 128;
    const int tid = threadIdx.x;
    const int tx  = tid & 15, ty = tid >> 4;
    const float* xb = x + b * CIN * Pn;

    float acc[8][8];
#pragma unroll
    for (int i = 0; i < 8; i++)
#pragma unroll
        for (int j = 0; j < 8; j++) acc[i][j] = 0.f;

    for (int k0 = 0; k0 < CIN; k0 += 8) {
#pragma unroll
        for (int i = 0; i < 4; i++) {      // A chunk: 128x8 = 1024
            int j = tid + 256 * i;
            int m = j >> 3, k = j & 7;
            As[k][m] = W1[m * CIN + k0 + k];
        }
#pragma unroll
        for (int i = 0; i < 4; i++) {      // B chunk: 8x128
            int j = tid + 256 * i;
            int r = j >> 7, n = j & 127;
            Bs[r][n] = (n0 + n < Pn) ? xb[(k0 + r) * Pn + n0 + n] : 0.f;
        }
        __syncthreads();
#pragma unroll
        for (int k = 0; k < 8; k++) {
            float a[8], bb[8];
#pragma unroll
            for (int i = 0; i < 8; i++) a[i] = As[k][ty * 8 + i];
#pragma unroll
            for (int j = 0; j < 8; j++) bb[j] = Bs[k][tx * 8 + j];
#pragma unroll
            for (int i = 0; i < 8; i++)
#pragma unroll
                for (int j = 0; j < 8; j++) acc[i][j] += a[i] * bb[j];
        }
        __syncthreads();
    }

#pragma unroll
    for (int i = 0; i < 8; i++) {
        int m = ty * 8 + i;
        float sc = s1[m], bi = b1[m];
        float* op = g_out1 + (b * CMID + m) * Pn;
#pragma unroll
        for (int j = 0; j < 8; j++) {
            int n = n0 + tx * 8 + j;
            if (n < Pn) op[n] = fmaxf(acc[i][j] * sc + bi, 0.f);
        }
    }
}

// ---------------------------------------------------------------------------
// Kernel 2: involution kernel generation (reduce 128->32 +BN+ReLU, span 32->392 +bias)
// grid (7, 16), 256 threads, 2 threads per pixel. 149 KB dynamic smem.
// ---------------------------------------------------------------------------
__global__ __launch_bounds__(256) void k_kgen(const float* __restrict__ Wr,
                                              const float* __restrict__ sr,
                                              const float* __restrict__ br,
                                              const float* __restrict__ Ws,
                                              const float* __restrict__ bs) {
    extern __shared__ float sm[];
    float* t1  = sm;              // [128 ch][128 px]         16384 f
    float* rsh = sm + 16384;      // [128 px][33 (pad)]        4224 f
    float* Wrs = rsh + 4224;      // [32][128]                 4096 f
    float* Wss = Wrs + 4096;      // [392][32]                12544 f

    const int b = blockIdx.y, n0 = blockIdx.x * 128, tid = threadIdx.x;
    const float* o1 = g_out1 + b * CMID * Pn;

#pragma unroll
    for (int i = 0; i < 64; i++) {
        int j = tid + 256 * i;
        int c = j >> 7, n = j & 127;
        t1[j] = (n0 + n < Pn) ? o1[c * Pn + n0 + n] : 0.f;
    }
#pragma unroll
    for (int i = 0; i < 16; i++) { int j = tid + 256 * i; Wrs[j] = Wr[j]; }
#pragma unroll
    for (int i = 0; i < 49; i++) { int j = tid + 256 * i; Wss[j] = Ws[j]; }
    __syncthreads();

    const int p = tid >> 1, half = tid & 1;

    // reduce: 16 r-values per thread
    float rv[16];
#pragma unroll
    for (int jj = 0; jj < 16; jj++) rv[jj] = 0.f;
    for (int c = 0; c < CMID; c++) {
        float xa = t1[c * 128 + p];
#pragma unroll
        for (int jj = 0; jj < 16; jj++)
            rv[jj] += Wrs[(half * 16 + jj) * 128 + c] * xa;
    }
#pragma unroll
    for (int jj = 0; jj < 16; jj++) {
        int j = half * 16 + jj;
        rsh[p * 33 + j] = fmaxf(rv[jj] * __ldg(sr + j) + __ldg(br + j), 0.f);
    }
    __syncthreads();

    // span: 196 w-rows per thread (rows half+2i), chunks of 28
    const bool valid = (n0 + p) < Pn;
    float* wout = g_w + b * CSPAN * Pn + n0 + p;
    for (int i0 = 0; i0 < 196; i0 += 28) {
        float acc[28];
#pragma unroll
        for (int ii = 0; ii < 28; ii++) acc[ii] = __ldg(bs + half + 2 * (i0 + ii));
        for (int k = 0; k < CRED; k++) {
            float rvv = rsh[p * 33 + k];
#pragma unroll
            for (int ii = 0; ii < 28; ii++)
                acc[ii] += Wss[(half + 2 * (i0 + ii)) * CRED + k] * rvv;
        }
        if (valid) {
#pragma unroll
            for (int ii = 0; ii < 28; ii++)
                wout[(half + 2 * (i0 + ii)) * Pn] = acc[ii];
        }
    }
}

// ---------------------------------------------------------------------------
// Kernel 3: involution apply. grid (2 half-planes, 8 groups, 16 batch).
// smem tile: 20 rows x 34 cols x 16 ch (channel-innermost for float4 LDS)
// ---------------------------------------------------------------------------
__global__ __launch_bounds__(256) void k_apply() {
    __shared__ __align__(16) float xs[20 * 34 * 16];
    const int y0 = blockIdx.x * 14;
    const int g  = blockIdx.y;
    const int b  = blockIdx.z;
    const int tid = threadIdx.x;

    const float* o1 = g_out1 + (b * CMID + g * 16) * Pn;
    for (int j = tid; j < 20 * 34 * 16; j += 256) {
        int c  = j & 15;
        int xx = (j >> 4) % 34;
        int yy = j / (16 * 34);
        int gy = y0 + yy - 3, gx = xx - 3;
        float v = 0.f;
        if (gy >= 0 && gy < 28 && gx >= 0 && gx < 28)
            v = o1[c * Pn + gy * 28 + gx];
        xs[j] = v;
    }
    __syncthreads();

    for (int idx = tid; idx < 14 * 28; idx += 256) {
        int y = idx / 28, xc = idx % 28;
        int hw = (y0 + y) * 28 + xc;
        const float* wp = g_w + (b * CSPAN + g * KK) * Pn + hw;
        float av[16];
#pragma unroll
        for (int c = 0; c < 16; c++) av[c] = 0.f;
#pragma unroll
        for (int k = 0; k < KK; k++) {
            float wk = wp[k * Pn];
            int dy = k / 7, dx = k % 7;
            const float4* v = (const float4*)&xs[((y + dy) * 34 + xc + dx) * 16];
            float4 v0 = v[0], v1 = v[1], v2 = v[2], v3 = v[3];
            av[0] += wk * v0.x; av[1] += wk * v0.y; av[2] += wk * v0.z; av[3] += wk * v0.w;
            av[4] += wk * v1.x; av[5] += wk * v1.y; av[6] += wk * v1.z; av[7] += wk * v1.w;
            av[8] += wk * v2.x; av[9] += wk * v2.y; av[10] += wk * v2.z; av[11] += wk * v2.w;
            av[12] += wk * v3.x; av[13] += wk * v3.y; av[14] += wk * v3.z; av[15] += wk * v3.w;
        }
        float* op = g_out2 + (b * CMID + g * 16) * Pn + hw;
#pragma unroll
        for (int c = 0; c < 16; c++) op[c * Pn] = av[c];
    }
}

// ---------------------------------------------------------------------------
// Kernel 4: conv3 1x1 (128->512) + BN + residual. grid (7, 16, 4 m-tiles)
// ---------------------------------------------------------------------------
__global__ __launch_bounds__(256) void k_conv3(const float* __restrict__ x,
                                               const float* __restrict__ W3,
                                               const float* __restrict__ s3,
                                               const float* __restrict__ b3,
                                               float* __restrict__ out) {
    __shared__ float As[8][132];
    __shared__ float Bs[8][128];
    const int b   = blockIdx.y;
    const int n0  = blockIdx.x * 128;
    const int mo  = blockIdx.z * 128;
    const int tid = threadIdx.x;
    const int tx  = tid & 15, ty = tid >> 4;
    const float* o2 = g_out2 + b * CMID * Pn;

    float acc[8][8];
#pragma unroll
    for (int i = 0; i < 8; i++)
#pragma unroll
        for (int j = 0; j < 8; j++) acc[i][j] = 0.f;

    for (int k0 = 0; k0 < CMID; k0 += 8) {
#pragma unroll
        for (int i = 0; i < 4; i++) {
            int j = tid + 256 * i;
            int m = j >> 3, k = j & 7;
            As[k][m] = W3[(mo + m) * CMID + k0 + k];
        }
#pragma unroll
        for (int i = 0; i < 4; i++) {
            int j = tid + 256 * i;
            int r = j >> 7, n = j & 127;
            Bs[r][n] = (n0 + n < Pn) ? o2[(k0 + r) * Pn + n0 + n] : 0.f;
        }
        __syncthreads();
#pragma unroll
        for (int k = 0; k < 8; k++) {
            float a[8], bb[8];
#pragma unroll
            for (int i = 0; i < 8; i++) a[i] = As[k][ty * 8 + i];
#pragma unroll
            for (int j = 0; j < 8; j++) bb[j] = Bs[k][tx * 8 + j];
#pragma unroll
            for (int i = 0; i < 8; i++)
#pragma unroll
                for (int j = 0; j < 8; j++) acc[i][j] += a[i] * bb[j];
        }
        __syncthreads();
    }

#pragma unroll
    for (int i = 0; i < 8; i++) {
        int m = mo + ty * 8 + i;
        float sc = s3[m], bi = b3[m];
        const float* xr = x + (b * CIN + m) * Pn;
        float* op = out + (b * CIN + m) * Pn;
#pragma unroll
        for (int j = 0; j < 8; j++) {
            int n = n0 + tx * 8 + j;
            if (n < Pn) op[n] = acc[i][j] * sc + bi + xr[n];
        }
    }
}

// ---------------------------------------------------------------------------
extern "C" void kernel_launch(void* const* d_in, const int* in_sizes, int n_in,
                              void* d_out, int out_size) {
    const float* x  = (const float*)d_in[0];
    const float* W1 = (const float*)d_in[1];
    const float* s1 = (const float*)d_in[2];
    const float* b1 = (const float*)d_in[3];
    const float* Wr = (const float*)d_in[4];
    const float* sr = (const float*)d_in[5];
    const float* br = (const float*)d_in[6];
    const float* Ws = (const float*)d_in[7];
    const float* bs = (const float*)d_in[8];
    const float* W3 = (const float*)d_in[9];
    const float* s3 = (const float*)d_in[10];
    const float* b3 = (const float*)d_in[11];
    float* out = (float*)d_out;

    const int kgen_smem = (16384 + 4224 + 4096 + 12544) * 4;  // 148,992 B
    cudaFuncSetAttribute(k_kgen, cudaFuncAttributeMaxDynamicSharedMemorySize, kgen_smem);

    k_conv1<<<dim3(7, 16), 256>>>(x, W1, s1, b1);
    k_kgen<<<dim3(7, 16), 256, kgen_smem>>>(Wr, sr, br, Ws, bs);
    k_apply<<<dim3(2, NG, BATCH), 256>>>();
    k_conv3<<<dim3(7, 16, 4), 256>>>(x, W3, s3, b3, out);
}

// round 2
// speedup vs baseline: 1.5966x; 1.5966x over previous
#include <cuda_runtime.h>

#define Pn    784
#define BATCH 16
#define CIN   512
#define CMID  128
#define CRED  32
#define NG    8
#define KK    49
#define CSPAN 392   // KK * NG

// Scratch (device globals: allocation-free rule)
__device__ float g_out1[BATCH * CMID * Pn];   // 6.4 MB
__device__ float g_w[BATCH * CSPAN * Pn];     // 19.7 MB
__device__ float g_out2[BATCH * CMID * Pn];   // 6.4 MB

// ---------------------------------------------------------------------------
// Conv 1x1 GEMM: C[128m, 128n] tile, BK=16, double-buffered, reg-staged.
// 256 threads, 8x8 microtile. Template: KTOT, ReLU, residual-add.
// ---------------------------------------------------------------------------
template<int KTOT, bool RELU_OUT, bool ADD_RESID>
__global__ __launch_bounds__(256) void k_conv(const float* __restrict__ W,
                                              const float* __restrict__ scale,
                                              const float* __restrict__ bias,
                                              const float* __restrict__ src,
                                              const float* __restrict__ resid,
                                              float* __restrict__ dst,
                                              int dst_ch) {
    __shared__ float As[2][16][128];
    __shared__ float Bs[2][16][128];
    const int b   = blockIdx.y;
    const int n0  = blockIdx.x * 128;
    const int mo  = blockIdx.z * 128;
    const int tid = threadIdx.x;
    const int tx  = tid & 15, ty = tid >> 4;
    const float* sb = src + b * KTOT * Pn;

    float acc[8][8];
#pragma unroll
    for (int i = 0; i < 8; i++)
#pragma unroll
        for (int j = 0; j < 8; j++) acc[i][j] = 0.f;

    float4 sa[2], sv[2];
    const int NT = KTOT / 16;

    // prologue: tile 0
#pragma unroll
    for (int i = 0; i < 2; i++) {
        int f = tid + 256 * i; int m = f >> 2, k4 = (f & 3) * 4;
        sa[i] = *(const float4*)&W[(mo + m) * KTOT + k4];
    }
#pragma unroll
    for (int i = 0; i < 2; i++) {
        int f = tid + 256 * i; int k = f >> 5, n4 = (f & 31) * 4;
        int n = n0 + n4;
        sv[i] = (n < Pn) ? *(const float4*)&sb[k * Pn + n] : make_float4(0.f,0.f,0.f,0.f);
    }
#pragma unroll
    for (int i = 0; i < 2; i++) {
        int f = tid + 256 * i; int m = f >> 2, k4 = (f & 3) * 4;
        As[0][k4+0][m] = sa[i].x; As[0][k4+1][m] = sa[i].y;
        As[0][k4+2][m] = sa[i].z; As[0][k4+3][m] = sa[i].w;
    }
#pragma unroll
    for (int i = 0; i < 2; i++) {
        int f = tid + 256 * i; int k = f >> 5, n4 = (f & 31) * 4;
        *(float4*)&Bs[0][k][n4] = sv[i];
    }
    __syncthreads();

#pragma unroll 1
    for (int t = 0; t < NT; t++) {
        if (t + 1 < NT) {   // issue next-tile global loads early
#pragma unroll
            for (int i = 0; i < 2; i++) {
                int f = tid + 256 * i; int m = f >> 2, k4 = (f & 3) * 4;
                sa[i] = *(const float4*)&W[(mo + m) * KTOT + (t + 1) * 16 + k4];
            }
#pragma unroll
            for (int i = 0; i < 2; i++) {
                int f = tid + 256 * i; int k = f >> 5, n4 = (f & 31) * 4;
                int n = n0 + n4;
                sv[i] = (n < Pn) ? *(const float4*)&sb[((t + 1) * 16 + k) * Pn + n]
                                 : make_float4(0.f,0.f,0.f,0.f);
            }
        }
        const int buf = t & 1;
#pragma unroll
        for (int k = 0; k < 16; k++) {
            float4 a0 = *(const float4*)&As[buf][k][ty * 8];
            float4 a1 = *(const float4*)&As[buf][k][ty * 8 + 4];
            float4 b0 = *(const float4*)&Bs[buf][k][tx * 8];
            float4 b1 = *(const float4*)&Bs[buf][k][tx * 8 + 4];
            float ar[8] = {a0.x,a0.y,a0.z,a0.w,a1.x,a1.y,a1.z,a1.w};
            float bc[8] = {b0.x,b0.y,b0.z,b0.w,b1.x,b1.y,b1.z,b1.w};
#pragma unroll
            for (int i = 0; i < 8; i++)
#pragma unroll
                for (int j = 0; j < 8; j++) acc[i][j] += ar[i] * bc[j];
        }
        if (t + 1 < NT) {
            const int nb = buf ^ 1;
#pragma unroll
            for (int i = 0; i < 2; i++) {
                int f = tid + 256 * i; int m = f >> 2, k4 = (f & 3) * 4;
                As[nb][k4+0][m] = sa[i].x; As[nb][k4+1][m] = sa[i].y;
                As[nb][k4+2][m] = sa[i].z; As[nb][k4+3][m] = sa[i].w;
            }
#pragma unroll
            for (int i = 0; i < 2; i++) {
                int f = tid + 256 * i; int k = f >> 5, n4 = (f & 31) * 4;
                *(float4*)&Bs[nb][k][n4] = sv[i];
            }
        }
        __syncthreads();
    }

    // epilogue
    const int nb0 = n0 + tx * 8;
    if (nb0 < Pn) {
#pragma unroll
        for (int i = 0; i < 8; i++) {
            int m = mo + ty * 8 + i;
            float sc = scale[m], bi = bias[m];
            float4 v0, v1;
            v0.x = acc[i][0]*sc+bi; v0.y = acc[i][1]*sc+bi;
            v0.z = acc[i][2]*sc+bi; v0.w = acc[i][3]*sc+bi;
            v1.x = acc[i][4]*sc+bi; v1.y = acc[i][5]*sc+bi;
            v1.z = acc[i][6]*sc+bi; v1.w = acc[i][7]*sc+bi;
            if (RELU_OUT) {
                v0.x = fmaxf(v0.x,0.f); v0.y = fmaxf(v0.y,0.f);
                v0.z = fmaxf(v0.z,0.f); v0.w = fmaxf(v0.w,0.f);
                v1.x = fmaxf(v1.x,0.f); v1.y = fmaxf(v1.y,0.f);
                v1.z = fmaxf(v1.z,0.f); v1.w = fmaxf(v1.w,0.f);
            }
            if (ADD_RESID) {
                const float* xr = resid + (b * dst_ch + m) * Pn + nb0;
                float4 r0 = *(const float4*)&xr[0];
                float4 r1 = *(const float4*)&xr[4];
                v0.x += r0.x; v0.y += r0.y; v0.z += r0.z; v0.w += r0.w;
                v1.x += r1.x; v1.y += r1.y; v1.z += r1.z; v1.w += r1.w;
            }
            float* op = dst + (b * dst_ch + m) * Pn + nb0;
            *(float4*)&op[0] = v0;
            *(float4*)&op[4] = v1;
        }
    }
}

// ---------------------------------------------------------------------------
// Kernel 2: involution kernel generation — register-tiled.
// reduce: R[32,128px] = Wr@t1 (4m x 4n microtile, 256 thr)
// span:   Wgen[392,128px] = Ws@R + bs (8m x 8n microtile, 49x16 units)
// ---------------------------------------------------------------------------
#define WRT_S 36   // padded k-row stride for WrT (16B aligned, conflict-light)

__global__ __launch_bounds__(256) void k_kgen(const float* __restrict__ Wr,
                                              const float* __restrict__ sr,
                                              const float* __restrict__ br,
                                              const float* __restrict__ Ws,
                                              const float* __restrict__ bs) {
    extern __shared__ float sm[];
    float* t1   = sm;                    // [128 c][128 n]       16384 f
    float* WrT  = t1 + 16384;            // [128 c][WRT_S]        4608 f
    float* rshT = WrT + 128 * WRT_S;     // [32 k][128 n]         4096 f
    float* WsT  = rshT + 4096;           // [32 k][392 m]        12544 f

    const int b = blockIdx.y, n0 = blockIdx.x * 128, tid = threadIdx.x;
    const float* o1 = g_out1 + b * CMID * Pn;

    // load t1 (c-major, float4 over n)
#pragma unroll
    for (int i = 0; i < 16; i++) {
        int j = tid + 256 * i;          // j < 4096 float4s
        int c = j >> 5, n4 = (j & 31) * 4;
        int n = n0 + n4;
        *(float4*)&t1[c * 128 + n4] =
            (n < Pn) ? *(const float4*)&o1[c * Pn + n] : make_float4(0.f,0.f,0.f,0.f);
    }
    // load WrT[c][m] = Wr[m][c]
#pragma unroll
    for (int i = 0; i < 16; i++) {
        int j = tid + 256 * i;          // j < 4096
        int m = j >> 7, c = j & 127;
        WrT[c * WRT_S + m] = Wr[j];
    }
    // load WsT[k][m] = Ws[m][k]
#pragma unroll
    for (int i = 0; i < 49; i++) {
        int j = tid + 256 * i;          // j < 12544
        int m = j >> 5, k = j & 31;
        WsT[k * 392 + m] = Ws[j];
    }
    __syncthreads();

    // ---- reduce: 4m x 4n per thread ----
    {
        const int mt = tid >> 5;         // 0..7 -> m = mt*4
        const int nn = (tid & 31) * 4;   // n
        float racc[4][4];
#pragma unroll
        for (int i = 0; i < 4; i++)
#pragma unroll
            for (int j = 0; j < 4; j++) racc[i][j] = 0.f;
#pragma unroll 8
        for (int c = 0; c < 128; c++) {
            float4 av = *(const float4*)&WrT[c * WRT_S + mt * 4];
            float4 bv = *(const float4*)&t1[c * 128 + nn];
            float ar[4] = {av.x, av.y, av.z, av.w};
            float bc[4] = {bv.x, bv.y, bv.z, bv.w};
#pragma unroll
            for (int i = 0; i < 4; i++)
#pragma unroll
                for (int j = 0; j < 4; j++) racc[i][j] += ar[i] * bc[j];
        }
#pragma unroll
        for (int i = 0; i < 4; i++) {
            int m = mt * 4 + i;
            float s = sr[m], bb = br[m];
            float4 v;
            v.x = fmaxf(racc[i][0]*s+bb, 0.f);
            v.y = fmaxf(racc[i][1]*s+bb, 0.f);
            v.z = fmaxf(racc[i][2]*s+bb, 0.f);
            v.w = fmaxf(racc[i][3]*s+bb, 0.f);
            *(float4*)&rshT[m * 128 + nn] = v;
        }
    }
    __syncthreads();

    // ---- span: 8m x 8n microtiles, 49x16 = 784 units over 256 threads ----
#pragma unroll 1
    for (int it = 0; it < 4; it++) {
        int unit = tid + 256 * it;
        if (unit >= 784) break;
        int mt = unit >> 4, nn = (unit & 15) * 8;   // m = mt*8, n = nn..nn+7
        float acc[8][8];
#pragma unroll
        for (int i = 0; i < 8; i++) {
            float bv = bs[mt * 8 + i];
#pragma unroll
            for (int j = 0; j < 8; j++) acc[i][j] = bv;
        }
#pragma unroll 8
        for (int k = 0; k < 32; k++) {
            float4 a0 = *(const float4*)&WsT[k * 392 + mt * 8];
            float4 a1 = *(const float4*)&WsT[k * 392 + mt * 8 + 4];
            float4 b0 = *(const float4*)&rshT[k * 128 + nn];
            float4 b1 = *(const float4*)&rshT[k * 128 + nn + 4];
            float ar[8] = {a0.x,a0.y,a0.z,a0.w,a1.x,a1.y,a1.z,a1.w};
            float bc[8] = {b0.x,b0.y,b0.z,b0.w,b1.x,b1.y,b1.z,b1.w};
#pragma unroll
            for (int i = 0; i < 8; i++)
#pragma unroll
                for (int j = 0; j < 8; j++) acc[i][j] += ar[i] * bc[j];
        }
        if (n0 + nn < Pn) {
#pragma unroll
            for (int i = 0; i < 8; i++) {
                int m = mt * 8 + i;
                float* wrow = g_w + (b * CSPAN + m) * Pn + n0 + nn;
                float4 v0 = {acc[i][0], acc[i][1], acc[i][2], acc[i][3]};
                float4 v1 = {acc[i][4], acc[i][5], acc[i][6], acc[i][7]};
                *(float4*)&wrow[0] = v0;
                *(float4*)&wrow[4] = v1;
            }
        }
    }
}

// ---------------------------------------------------------------------------
// Kernel 3: involution apply. grid (2 half-planes, 8 groups, 16 batch).
// smem tile: [20 rows x 34 cols] px-slots, channel-inner, slot stride 20 floats
// (80B, 16B-aligned, breaks the 64B-stride bank conflict).
// ---------------------------------------------------------------------------
#define APL_SLOT 20
#define APL_SMEM (20 * 34 * APL_SLOT * 4)   // 54400 B (dynamic)

__global__ __launch_bounds__(256) void k_apply() {
    extern __shared__ __align__(16) float xs[];
    const int y0 = blockIdx.x * 14;
    const int g  = blockIdx.y;
    const int b  = blockIdx.z;
    const int tid = threadIdx.x;

    const float* o1 = g_out1 + (b * CMID + g * 16) * Pn;
    for (int j = tid; j < 20 * 34 * 16; j += 256) {
        int c    = j & 15;
        int slot = j >> 4;
        int xx = slot % 34, yy = slot / 34;
        int gy = y0 + yy - 3, gx = xx - 3;
        float v = 0.f;
        if (gy >= 0 && gy < 28 && gx >= 0 && gx < 28)
            v = o1[c * Pn + gy * 28 + gx];
        xs[slot * APL_SLOT + c] = v;
    }
    __syncthreads();

    for (int idx = tid; idx < 14 * 28; idx += 256) {
        int y = idx / 28, xc = idx % 28;
        int hw = (y0 + y) * 28 + xc;
        const float* wp = g_w + (b * CSPAN + g * KK) * Pn + hw;
        float av[16];
#pragma unroll
        for (int c = 0; c < 16; c++) av[c] = 0.f;
#pragma unroll
        for (int k = 0; k < KK; k++) {
            float wk = wp[k * Pn];
            int dy = k / 7, dx = k % 7;
            const float* base = &xs[((y + dy) * 34 + xc + dx) * APL_SLOT];
            float4 v0 = *(const float4*)&base[0];
            float4 v1 = *(const float4*)&base[4];
            float4 v2 = *(const float4*)&base[8];
            float4 v3 = *(const float4*)&base[12];
            av[0] += wk*v0.x; av[1] += wk*v0.y; av[2] += wk*v0.z; av[3] += wk*v0.w;
            av[4] += wk*v1.x; av[5] += wk*v1.y; av[6] += wk*v1.z; av[7] += wk*v1.w;
            av[8] += wk*v2.x; av[9] += wk*v2.y; av[10]+= wk*v2.z; av[11]+= wk*v2.w;
            av[12]+= wk*v3.x; av[13]+= wk*v3.y; av[14]+= wk*v3.z; av[15]+= wk*v3.w;
        }
        float* op = g_out2 + (b * CMID + g * 16) * Pn + hw;
#pragma unroll
        for (int c = 0; c < 16; c++) op[c * Pn] = av[c];
    }
}

// ---------------------------------------------------------------------------
extern "C" void kernel_launch(void* const* d_in, const int* in_sizes, int n_in,
                              void* d_out, int out_size) {
    const float* x  = (const float*)d_in[0];
    const float* W1 = (const float*)d_in[1];
    const float* s1 = (const float*)d_in[2];
    const float* b1 = (const float*)d_in[3];
    const float* Wr = (const float*)d_in[4];
    const float* sr = (const float*)d_in[5];
    const float* br = (const float*)d_in[6];
    const float* Ws = (const float*)d_in[7];
    const float* bs = (const float*)d_in[8];
    const float* W3 = (const float*)d_in[9];
    const float* s3 = (const float*)d_in[10];
    const float* b3 = (const float*)d_in[11];
    float* out = (float*)d_out;

    const int kgen_smem = (16384 + 128 * WRT_S + 4096 + 12544) * 4;  // 150,528 B
    cudaFuncSetAttribute(k_kgen, cudaFuncAttributeMaxDynamicSharedMemorySize, kgen_smem);
    cudaFuncSetAttribute(k_apply, cudaFuncAttributeMaxDynamicSharedMemorySize, APL_SMEM);

    float* o1p = nullptr; cudaGetSymbolAddress((void**)&o1p, g_out1);
    float* o2p = nullptr; cudaGetSymbolAddress((void**)&o2p, g_out2);

    // conv1: 512 -> 128, ReLU
    k_conv<CIN, true, false><<<dim3(7, 16, 1), 256>>>(W1, s1, b1, x, nullptr, o1p, CMID);
    // kernel generation
    k_kgen<<<dim3(7, 16), 256, kgen_smem>>>(Wr, sr, br, Ws, bs);
    // involution apply
    k_apply<<<dim3(2, NG, BATCH), 256, APL_SMEM>>>();
    // conv3: 128 -> 512, + BN + residual
    k_conv<CMID, false, true><<<dim3(7, 16, 4), 256>>>(W3, s3, b3, o2p, x, out, CIN);
}

// round 4
// speedup vs baseline: 2.0826x; 1.3043x over previous
#include <cuda_runtime.h>
#include <cuda_bf16.h>
#include <cstdint>

#define Pn    784
#define BATCH 16
#define CIN   512
#define CMID  128
#define CRED  32
#define NG    8
#define KK    49
#define CSPAN 392   // KK * NG

// Scratch (device globals: allocation-free rule)
__device__ float g_out1[BATCH * CMID * Pn];   // 6.4 MB
__device__ float g_w[BATCH * CSPAN * Pn];     // 19.7 MB
__device__ float g_out2[BATCH * CMID * Pn];   // 6.4 MB

// ============================================================================
// mma.sync helpers (sm_80+ PTX — valid for compute_100)
// ============================================================================
__device__ __forceinline__ uint32_t smem_u32(const void* p) {
    uint32_t a;
    asm("{ .reg .u64 t; cvta.to.shared.u64 t, %1; cvt.u32.u64 %0, t; }"
        : "=r"(a) : "l"(p));
    return a;
}
__device__ __forceinline__ void mma_bf16(float* d, const uint32_t* a, const uint32_t* b) {
    asm volatile(
        "mma.sync.aligned.m16n8k16.row.col.f32.bf16.bf16.f32 "
        "{%0,%1,%2,%3}, {%4,%5,%6,%7}, {%8,%9}, {%0,%1,%2,%3};"
        : "+f"(d[0]), "+f"(d[1]), "+f"(d[2]), "+f"(d[3])
        : "r"(a[0]), "r"(a[1]), "r"(a[2]), "r"(a[3]), "r"(b[0]), "r"(b[1]));
}
__device__ __forceinline__ void ldsm_x4(uint32_t* r, uint32_t addr) {
    asm volatile("ldmatrix.sync.aligned.m8n8.x4.shared.b16 {%0,%1,%2,%3}, [%4];"
        : "=r"(r[0]), "=r"(r[1]), "=r"(r[2]), "=r"(r[3]) : "r"(addr));
}
__device__ __forceinline__ void ldsm_x2(uint32_t* r, uint32_t addr) {
    asm volatile("ldmatrix.sync.aligned.m8n8.x2.shared.b16 {%0,%1}, [%2];"
        : "=r"(r[0]), "=r"(r[1]) : "r"(addr));
}
__device__ __forceinline__ void split2(float f, __nv_bfloat16& h, __nv_bfloat16& l) {
    h = __float2bfloat16(f);
    l = __float2bfloat16(f - __bfloat162float(h));
}
__device__ __forceinline__ uint32_t pk2(__nv_bfloat16 a, __nv_bfloat16 b) {
    __nv_bfloat162 t = __halves2bfloat162(a, b);
    return *reinterpret_cast<uint32_t*>(&t);
}

// ============================================================================
// Split-bf16 tensor-core 1x1-conv GEMM (mma.sync m16n8k16).
// D[128m, 112n] = W[mo:mo+128, :KTOT] @ src[b, :KTOT, n0:n0+112]
// 3-term: D += Ah*Bh + Ah*Bl + Al*Bh.  Epilogue: BN (+ReLU) (+residual).
// ============================================================================
#define BM 128
#define BN 112
#define KC 64
#define SK 72                       // padded k-stride (bf16 elems) — conflict-free ldmatrix
#define A_E (BM * SK)               // 9216 bf16
#define B_E (BN * SK)               // 8064 bf16
#define STG_E (2 * A_E + 2 * B_E)   // 34560 bf16 per stage
#define CONV_SMEM (2 * STG_E * 2)   // 138240 bytes

template<int KTOT, bool RELU_OUT, bool ADD_RESID>
__global__ __launch_bounds__(256) void k_convmm(const float* __restrict__ W,
                                                const float* __restrict__ scale,
                                                const float* __restrict__ bias,
                                                const float* __restrict__ src,
                                                const float* __restrict__ resid,
                                                float* __restrict__ dst,
                                                int dst_ch) {
    extern __shared__ __align__(16) __nv_bfloat16 smb[];
    const int tid  = threadIdx.x;
    const int wid  = tid >> 5, lane = tid & 31;
    const int b    = blockIdx.y;
    const int n0   = blockIdx.x * BN;
    const int mo   = blockIdx.z * BM;
    const int warp_m = (wid >> 1) * 32;
    const int warp_n = (wid & 1) * 56;
    const float* sb = src + (size_t)b * KTOT * Pn;
    const uint32_t sbase = smem_u32(smb);

    float acc[2][7][4];
#pragma unroll
    for (int i = 0; i < 2; i++)
#pragma unroll
        for (int j = 0; j < 7; j++)
#pragma unroll
            for (int q = 0; q < 4; q++) acc[i][j][q] = 0.f;

    const int NT = KTOT / KC;
    float4 sa[8], sv[7];

    // ---- LDG tile 0 ----
#pragma unroll
    for (int i = 0; i < 8; i++) {
        int u = tid + 256 * i; int m = u >> 4; int k4 = (u & 15) * 4;
        sa[i] = *(const float4*)&W[(size_t)(mo + m) * KTOT + k4];
    }
#pragma unroll
    for (int i = 0; i < 7; i++) {
        int u = tid + 256 * i; int k = u / 28; int n4 = (u - k * 28) * 4;
        sv[i] = *(const float4*)&sb[(size_t)k * Pn + n0 + n4];
    }

#pragma unroll 1
    for (int t = 0; t < NT; t++) {
        const int buf = t & 1;
        // ---- convert + STS tile t ----
        {
            __nv_bfloat16* aHi = smb + buf * STG_E;
            __nv_bfloat16* aLo = aHi + A_E;
            __nv_bfloat16* bHi = aLo + A_E;
            __nv_bfloat16* bLo = bHi + B_E;
#pragma unroll
            for (int i = 0; i < 8; i++) {
                int u = tid + 256 * i; int m = u >> 4; int k4 = (u & 15) * 4;
                __nv_bfloat16 h0,h1,h2,h3,l0,l1,l2,l3;
                split2(sa[i].x, h0, l0); split2(sa[i].y, h1, l1);
                split2(sa[i].z, h2, l2); split2(sa[i].w, h3, l3);
                *(uint2*)&aHi[m * SK + k4] = make_uint2(pk2(h0,h1), pk2(h2,h3));
                *(uint2*)&aLo[m * SK + k4] = make_uint2(pk2(l0,l1), pk2(l2,l3));
            }
#pragma unroll
            for (int i = 0; i < 7; i++) {
                int u = tid + 256 * i; int k = u / 28; int n4 = (u - k * 28) * 4;
                float f[4] = {sv[i].x, sv[i].y, sv[i].z, sv[i].w};
#pragma unroll
                for (int j = 0; j < 4; j++) {
                    __nv_bfloat16 h, l; split2(f[j], h, l);
                    bHi[(n4 + j) * SK + k] = h;
                    bLo[(n4 + j) * SK + k] = l;
                }
            }
        }
        // ---- LDG tile t+1 (overlaps the mma below) ----
        if (t + 1 < NT) {
#pragma unroll
            for (int i = 0; i < 8; i++) {
                int u = tid + 256 * i; int m = u >> 4; int k4 = (u & 15) * 4;
                sa[i] = *(const float4*)&W[(size_t)(mo + m) * KTOT + (t + 1) * KC + k4];
            }
#pragma unroll
            for (int i = 0; i < 7; i++) {
                int u = tid + 256 * i; int k = u / 28; int n4 = (u - k * 28) * 4;
                sv[i] = *(const float4*)&sb[(size_t)((t + 1) * KC + k) * Pn + n0 + n4];
            }
        }
        __syncthreads();

        // ---- mma on tile t ----
        {
            const uint32_t aHiB = sbase + buf * STG_E * 2;
            const uint32_t dLoA = A_E * 2;            // aLo - aHi (bytes)
            const uint32_t bHiB = aHiB + 2 * A_E * 2;
            const uint32_t dLoB = B_E * 2;
            const int l15 = lane & 15, l7 = lane & 7;
            const uint32_t aRow = (uint32_t)(warp_m + l15) * SK + ((lane >> 4) & 1) * 8;
#pragma unroll
            for (int ks = 0; ks < 4; ks++) {
                uint32_t ah[2][4], al[2][4], bh[7][2], bl[7][2];
#pragma unroll
                for (int i = 0; i < 2; i++) {
                    uint32_t ad = aHiB + (aRow + (uint32_t)(i * 16 * SK + ks * 16)) * 2;
                    ldsm_x4(ah[i], ad);
                    ldsm_x4(al[i], ad + dLoA);
                }
#pragma unroll
                for (int jp = 0; jp < 3; jp++) {
                    uint32_t bd = bHiB +
                        ((uint32_t)(warp_n + (jp * 2 + (lane >> 4)) * 8 + l7) * SK
                         + ks * 16 + ((lane >> 3) & 1) * 8) * 2;
                    uint32_t r[4];
                    ldsm_x4(r, bd);
                    bh[jp*2][0]=r[0]; bh[jp*2][1]=r[1]; bh[jp*2+1][0]=r[2]; bh[jp*2+1][1]=r[3];
                    ldsm_x4(r, bd + dLoB);
                    bl[jp*2][0]=r[0]; bl[jp*2][1]=r[1]; bl[jp*2+1][0]=r[2]; bl[jp*2+1][1]=r[3];
                }
                {
                    uint32_t bd = bHiB +
                        ((uint32_t)(warp_n + 48 + l7) * SK
                         + ks * 16 + ((lane >> 3) & 1) * 8) * 2;
                    ldsm_x2(bh[6], bd);
                    ldsm_x2(bl[6], bd + dLoB);
                }
#pragma unroll
                for (int i = 0; i < 2; i++)
#pragma unroll
                    for (int j = 0; j < 7; j++) {
                        mma_bf16(acc[i][j], ah[i], bh[j]);
                        mma_bf16(acc[i][j], ah[i], bl[j]);
                        mma_bf16(acc[i][j], al[i], bh[j]);
                    }
            }
        }
    }

    // ---- epilogue: BN (+ReLU) (+residual), straight from registers ----
    const int r0 = lane >> 2;
    const int c0 = (lane & 3) * 2;
#pragma unroll
    for (int i = 0; i < 2; i++) {
        const int mA = mo + warp_m + i * 16 + r0;
        const int mB = mA + 8;
        const float scA = scale[mA], biA = bias[mA];
        const float scB = scale[mB], biB = bias[mB];
        float* dA = dst + ((size_t)b * dst_ch + mA) * Pn;
        float* dB = dst + ((size_t)b * dst_ch + mB) * Pn;
        const float* rA = ADD_RESID ? resid + ((size_t)b * dst_ch + mA) * Pn : nullptr;
        const float* rB = ADD_RESID ? resid + ((size_t)b * dst_ch + mB) * Pn : nullptr;
#pragma unroll
        for (int j = 0; j < 7; j++) {
            const int n = n0 + warp_n + j * 8 + c0;
            float2 vA = {acc[i][j][0] * scA + biA, acc[i][j][1] * scA + biA};
            float2 vB = {acc[i][j][2] * scB + biB, acc[i][j][3] * scB + biB};
            if (RELU_OUT) {
                vA.x = fmaxf(vA.x, 0.f); vA.y = fmaxf(vA.y, 0.f);
                vB.x = fmaxf(vB.x, 0.f); vB.y = fmaxf(vB.y, 0.f);
            }
            if (ADD_RESID) {
                float2 qA = *(const float2*)&rA[n];
                float2 qB = *(const float2*)&rB[n];
                vA.x += qA.x; vA.y += qA.y;
                vB.x += qB.x; vB.y += qB.y;
            }
            *(float2*)&dA[n] = vA;
            *(float2*)&dB[n] = vB;
        }
    }
}

// ---------------------------------------------------------------------------
// Kernel 2: involution kernel generation — register-tiled (unchanged, working)
// ---------------------------------------------------------------------------
#define WRT_S 36

__global__ __launch_bounds__(256) void k_kgen(const float* __restrict__ Wr,
                                              const float* __restrict__ sr,
                                              const float* __restrict__ br,
                                              const float* __restrict__ Ws,
                                              const float* __restrict__ bs) {
    extern __shared__ float smk[];
    float* t1   = smk;
    float* WrT  = t1 + 16384;
    float* rshT = WrT + 128 * WRT_S;
    float* WsT  = rshT + 4096;

    const int b = blockIdx.y, n0 = blockIdx.x * 128, tid = threadIdx.x;
    const float* o1 = g_out1 + b * CMID * Pn;

#pragma unroll
    for (int i = 0; i < 16; i++) {
        int j = tid + 256 * i;
        int c = j >> 5, n4 = (j & 31) * 4;
        int n = n0 + n4;
        *(float4*)&t1[c * 128 + n4] =
            (n < Pn) ? *(const float4*)&o1[c * Pn + n] : make_float4(0.f,0.f,0.f,0.f);
    }
#pragma unroll
    for (int i = 0; i < 16; i++) {
        int j = tid + 256 * i;
        int m = j >> 7, c = j & 127;
        WrT[c * WRT_S + m] = Wr[j];
    }
#pragma unroll
    for (int i = 0; i < 49; i++) {
        int j = tid + 256 * i;
        int m = j >> 5, k = j & 31;
        WsT[k * 392 + m] = Ws[j];
    }
    __syncthreads();

    {
        const int mt = tid >> 5;
        const int nn = (tid & 31) * 4;
        float racc[4][4];
#pragma unroll
        for (int i = 0; i < 4; i++)
#pragma unroll
            for (int j = 0; j < 4; j++) racc[i][j] = 0.f;
#pragma unroll 8
        for (int c = 0; c < 128; c++) {
            float4 av = *(const float4*)&WrT[c * WRT_S + mt * 4];
            float4 bv = *(const float4*)&t1[c * 128 + nn];
            float ar[4] = {av.x, av.y, av.z, av.w};
            float bc[4] = {bv.x, bv.y, bv.z, bv.w};
#pragma unroll
            for (int i = 0; i < 4; i++)
#pragma unroll
                for (int j = 0; j < 4; j++) racc[i][j] += ar[i] * bc[j];
        }
#pragma unroll
        for (int i = 0; i < 4; i++) {
            int m = mt * 4 + i;
            float s = sr[m], bb = br[m];
            float4 v;
            v.x = fmaxf(racc[i][0]*s+bb, 0.f);
            v.y = fmaxf(racc[i][1]*s+bb, 0.f);
            v.z = fmaxf(racc[i][2]*s+bb, 0.f);
            v.w = fmaxf(racc[i][3]*s+bb, 0.f);
            *(float4*)&rshT[m * 128 + nn] = v;
        }
    }
    __syncthreads();

#pragma unroll 1
    for (int it = 0; it < 4; it++) {
        int unit = tid + 256 * it;
        if (unit >= 784) break;
        int mt = unit >> 4, nn = (unit & 15) * 8;
        float acc[8][8];
#pragma unroll
        for (int i = 0; i < 8; i++) {
            float bv = bs[mt * 8 + i];
#pragma unroll
            for (int j = 0; j < 8; j++) acc[i][j] = bv;
        }
#pragma unroll 8
        for (int k = 0; k < 32; k++) {
            float4 a0 = *(const float4*)&WsT[k * 392 + mt * 8];
            float4 a1 = *(const float4*)&WsT[k * 392 + mt * 8 + 4];
            float4 b0 = *(const float4*)&rshT[k * 128 + nn];
            float4 b1 = *(const float4*)&rshT[k * 128 + nn + 4];
            float ar[8] = {a0.x,a0.y,a0.z,a0.w,a1.x,a1.y,a1.z,a1.w};
            float bc[8] = {b0.x,b0.y,b0.z,b0.w,b1.x,b1.y,b1.z,b1.w};
#pragma unroll
            for (int i = 0; i < 8; i++)
#pragma unroll
                for (int j = 0; j < 8; j++) acc[i][j] += ar[i] * bc[j];
        }
        if (n0 + nn < Pn) {
#pragma unroll
            for (int i = 0; i < 8; i++) {
                int m = mt * 8 + i;
                float* wrow = g_w + (b * CSPAN + m) * Pn + n0 + nn;
                float4 v0 = {acc[i][0], acc[i][1], acc[i][2], acc[i][3]};
                float4 v1 = {acc[i][4], acc[i][5], acc[i][6], acc[i][7]};
                *(float4*)&wrow[0] = v0;
                *(float4*)&wrow[4] = v1;
            }
        }
    }
}

// ---------------------------------------------------------------------------
// Kernel 3: involution apply (unchanged, working)
// ---------------------------------------------------------------------------
#define APL_SLOT 20
#define APL_SMEM (20 * 34 * APL_SLOT * 4)

__global__ __launch_bounds__(256) void k_apply() {
    extern __shared__ __align__(16) float xs[];
    const int y0 = blockIdx.x * 14;
    const int g  = blockIdx.y;
    const int b  = blockIdx.z;
    const int tid = threadIdx.x;

    const float* o1 = g_out1 + (b * CMID + g * 16) * Pn;
    for (int j = tid; j < 20 * 34 * 16; j += 256) {
        int c    = j & 15;
        int slot = j >> 4;
        int xx = slot % 34, yy = slot / 34;
        int gy = y0 + yy - 3, gx = xx - 3;
        float v = 0.f;
        if (gy >= 0 && gy < 28 && gx >= 0 && gx < 28)
            v = o1[c * Pn + gy * 28 + gx];
        xs[slot * APL_SLOT + c] = v;
    }
    __syncthreads();

    for (int idx = tid; idx < 14 * 28; idx += 256) {
        int y = idx / 28, xc = idx % 28;
        int hw = (y0 + y) * 28 + xc;
        const float* wp = g_w + (b * CSPAN + g * KK) * Pn + hw;
        float av[16];
#pragma unroll
        for (int c = 0; c < 16; c++) av[c] = 0.f;
#pragma unroll
        for (int k = 0; k < KK; k++) {
            float wk = wp[k * Pn];
            int dy = k / 7, dx = k % 7;
            const float* base = &xs[((y + dy) * 34 + xc + dx) * APL_SLOT];
            float4 v0 = *(const float4*)&base[0];
            float4 v1 = *(const float4*)&base[4];
            float4 v2 = *(const float4*)&base[8];
            float4 v3 = *(const float4*)&base[12];
            av[0] += wk*v0.x; av[1] += wk*v0.y; av[2] += wk*v0.z; av[3] += wk*v0.w;
            av[4] += wk*v1.x; av[5] += wk*v1.y; av[6] += wk*v1.z; av[7] += wk*v1.w;
            av[8] += wk*v2.x; av[9] += wk*v2.y; av[10]+= wk*v2.z; av[11]+= wk*v2.w;
            av[12]+= wk*v3.x; av[13]+= wk*v3.y; av[14]+= wk*v3.z; av[15]+= wk*v3.w;
        }
        float* op = g_out2 + (b * CMID + g * 16) * Pn + hw;
#pragma unroll
        for (int c = 0; c < 16; c++) op[c * Pn] = av[c];
    }
}

// ---------------------------------------------------------------------------
extern "C" void kernel_launch(void* const* d_in, const int* in_sizes, int n_in,
                              void* d_out, int out_size) {
    const float* x  = (const float*)d_in[0];
    const float* W1 = (const float*)d_in[1];
    const float* s1 = (const float*)d_in[2];
    const float* b1 = (const float*)d_in[3];
    const float* Wr = (const float*)d_in[4];
    const float* sr = (const float*)d_in[5];
    const float* br = (const float*)d_in[6];
    const float* Ws = (const float*)d_in[7];
    const float* bs = (const float*)d_in[8];
    const float* W3 = (const float*)d_in[9];
    const float* s3 = (const float*)d_in[10];
    const float* b3 = (const float*)d_in[11];
    float* out = (float*)d_out;

    const int kgen_smem = (16384 + 128 * WRT_S + 4096 + 12544) * 4;
    cudaFuncSetAttribute(k_kgen, cudaFuncAttributeMaxDynamicSharedMemorySize, kgen_smem);
    cudaFuncSetAttribute(k_apply, cudaFuncAttributeMaxDynamicSharedMemorySize, APL_SMEM);
    cudaFuncSetAttribute(k_convmm<CIN, true, false>,
                         cudaFuncAttributeMaxDynamicSharedMemorySize, CONV_SMEM);
    cudaFuncSetAttribute(k_convmm<CMID, false, true>,
                         cudaFuncAttributeMaxDynamicSharedMemorySize, CONV_SMEM);

    float* o1p = nullptr; cudaGetSymbolAddress((void**)&o1p, g_out1);
    float* o2p = nullptr; cudaGetSymbolAddress((void**)&o2p, g_out2);

    // conv1: 512 -> 128, BN+ReLU
    k_convmm<CIN, true, false><<<dim3(7, 16, 1), 256, CONV_SMEM>>>(
        W1, s1, b1, x, nullptr, o1p, CMID);
    // involution kernel generation
    k_kgen<<<dim3(7, 16), 256, kgen_smem>>>(Wr, sr, br, Ws, bs);
    // involution apply
    k_apply<<<dim3(2, NG, BATCH), 256, APL_SMEM>>>();
    // conv3: 128 -> 512, BN + residual
    k_convmm<CMID, false, true><<<dim3(7, 16, 4), 256, CONV_SMEM>>>(
        W3, s3, b3, o2p, x, out, CIN);
}

// round 5
// speedup vs baseline: 3.0022x; 1.4416x over previous
#include <cuda_runtime.h>
#include <cuda_bf16.h>
#include <cstdint>

#define Pn    784
#define BATCH 16
#define CIN   512
#define CMID  128
#define CRED  32
#define NG    8
#define KK    49
#define CSPAN 392   // KK * NG

// Scratch (device globals: allocation-free rule)
__device__ float g_out1[BATCH * CMID * Pn];                 // 6.4 MB
__device__ float g_w[BATCH * CSPAN * Pn];                   // 19.7 MB
__device__ __nv_bfloat16 g_o2h[BATCH * CMID * Pn];          // 3.2 MB
__device__ __nv_bfloat16 g_o2l[BATCH * CMID * Pn];          // 3.2 MB
__device__ __nv_bfloat16 g_w3h[CIN * CMID];
__device__ __nv_bfloat16 g_w3l[CIN * CMID];

// ============================================================================
// helpers
// ============================================================================
__device__ __forceinline__ uint32_t smem_u32(const void* p) {
    uint32_t a;
    asm("{ .reg .u64 t; cvta.to.shared.u64 t, %1; cvt.u32.u64 %0, t; }"
        : "=r"(a) : "l"(p));
    return a;
}
__device__ __forceinline__ void mma_bf16(float* d, const uint32_t* a, const uint32_t* b) {
    asm volatile(
        "mma.sync.aligned.m16n8k16.row.col.f32.bf16.bf16.f32 "
        "{%0,%1,%2,%3}, {%4,%5,%6,%7}, {%8,%9}, {%0,%1,%2,%3};"
        : "+f"(d[0]), "+f"(d[1]), "+f"(d[2]), "+f"(d[3])
        : "r"(a[0]), "r"(a[1]), "r"(a[2]), "r"(a[3]), "r"(b[0]), "r"(b[1]));
}
__device__ __forceinline__ void ldsm_x4(uint32_t* r, uint32_t a) {
    asm volatile("ldmatrix.sync.aligned.m8n8.x4.shared.b16 {%0,%1,%2,%3}, [%4];"
        : "=r"(r[0]), "=r"(r[1]), "=r"(r[2]), "=r"(r[3]) : "r"(a));
}
__device__ __forceinline__ void ldsm_x4_t(uint32_t* r, uint32_t a) {
    asm volatile("ldmatrix.sync.aligned.m8n8.x4.trans.shared.b16 {%0,%1,%2,%3}, [%4];"
        : "=r"(r[0]), "=r"(r[1]), "=r"(r[2]), "=r"(r[3]) : "r"(a));
}
__device__ __forceinline__ void ldsm_x2_t(uint32_t* r, uint32_t a) {
    asm volatile("ldmatrix.sync.aligned.m8n8.x2.trans.shared.b16 {%0,%1}, [%2];"
        : "=r"(r[0]), "=r"(r[1]) : "r"(a));
}
__device__ __forceinline__ void cpa16(uint32_t dst, const void* src) {
    asm volatile("cp.async.ca.shared.global [%0], [%1], 16;" :: "r"(dst), "l"(src));
}
#define CP_COMMIT() asm volatile("cp.async.commit_group;" ::: "memory")
#define CP_WAIT0()  asm volatile("cp.async.wait_group 0;" ::: "memory")

__device__ __forceinline__ void split2(float f, __nv_bfloat16& h, __nv_bfloat16& l) {
    h = __float2bfloat16(f);
    l = __float2bfloat16(f - __bfloat162float(h));
}
__device__ __forceinline__ uint32_t pk2(__nv_bfloat16 a, __nv_bfloat16 b) {
    __nv_bfloat162 t = __halves2bfloat162(a, b);
    return *reinterpret_cast<uint32_t*>(&t);
}

// ============================================================================
// Shared GEMM tile geometry. A [128m][SK k] row-major, B [KC k][SN n] row-major
// (consumed via ldmatrix.trans). Split-bf16 3-term accumulation.
// ============================================================================
#define BM 128
#define BN 112
#define KC 64
#define SK 72
#define SN 120
#define A_E (BM * SK)               // 9216 elems / plane
#define B_E (KC * SN)               // 7680 elems / plane
#define STG_E (2 * A_E + 2 * B_E)   // 33792 elems = 67584 B
#define AEb (A_E * 2)
#define BEb (B_E * 2)

__device__ __forceinline__ void mma_chunk(float (&acc)[2][7][4],
                                          uint32_t aHiB, uint32_t bHiB,
                                          int lane, int warp_m, int warp_n) {
    const int l15 = lane & 15, l7 = lane & 7;
    const uint32_t aRow = (uint32_t)(warp_m + l15) * SK + ((lane >> 4) & 1) * 8;
#pragma unroll
    for (int ks = 0; ks < 4; ks++) {
        uint32_t ah[2][4], al[2][4];
#pragma unroll
        for (int i = 0; i < 2; i++) {
            uint32_t ad = aHiB + (aRow + (uint32_t)(i * 16 * SK + ks * 16)) * 2;
            ldsm_x4(ah[i], ad);
            ldsm_x4(al[i], ad + AEb);
        }
#pragma unroll
        for (int jp = 0; jp < 3; jp++) {
            uint32_t kr = (uint32_t)(ks * 16 + l7 + ((lane >> 3) & 1) * 8);
            uint32_t nc = (uint32_t)(warp_n + jp * 16 + (lane >> 4) * 8);
            uint32_t bd = bHiB + (kr * SN + nc) * 2;
            uint32_t rh[4], rl[4];
            ldsm_x4_t(rh, bd);
            ldsm_x4_t(rl, bd + BEb);
#pragma unroll
            for (int i = 0; i < 2; i++) {
                mma_bf16(acc[i][2*jp],   ah[i], rh + 0);
                mma_bf16(acc[i][2*jp],   ah[i], rl + 0);
                mma_bf16(acc[i][2*jp],   al[i], rh + 0);
                mma_bf16(acc[i][2*jp+1], ah[i], rh + 2);
                mma_bf16(acc[i][2*jp+1], ah[i], rl + 2);
                mma_bf16(acc[i][2*jp+1], al[i], rh + 2);
            }
        }
        {
            uint32_t kr = (uint32_t)(ks * 16 + l15);
            uint32_t bd = bHiB + (kr * SN + (uint32_t)(warp_n + 48)) * 2;
            uint32_t rh[2], rl[2];
            ldsm_x2_t(rh, bd);
            ldsm_x2_t(rl, bd + BEb);
#pragma unroll
            for (int i = 0; i < 2; i++) {
                mma_bf16(acc[i][6], ah[i], rh);
                mma_bf16(acc[i][6], ah[i], rl);
                mma_bf16(acc[i][6], al[i], rh);
            }
        }
    }
}

// ============================================================================
// conv1: 512->128, BN+ReLU. fp32 in-kernel split, double-buffered, reg-staged.
// grid (7, 16), 256 thr, 1 CTA/SM, K pipeline depth 8.
// ============================================================================
#define CONV1_SMEM (2 * STG_E * 2)   // 135168 B

__global__ __launch_bounds__(256) void k_conv1mm(const float* __restrict__ W,
                                                 const float* __restrict__ scale,
                                                 const float* __restrict__ bias,
                                                 const float* __restrict__ x) {
    extern __shared__ __align__(16) __nv_bfloat16 smb[];
    const int tid = threadIdx.x, wid = tid >> 5, lane = tid & 31;
    const int b = blockIdx.y, n0 = blockIdx.x * BN;
    const int warp_m = (wid >> 1) * 32, warp_n = (wid & 1) * 56;
    const float* sb = x + (size_t)b * CIN * Pn;
    const uint32_t sbase = smem_u32(smb);

    float acc[2][7][4];
#pragma unroll
    for (int i = 0; i < 2; i++)
#pragma unroll
        for (int j = 0; j < 7; j++)
#pragma unroll
            for (int q = 0; q < 4; q++) acc[i][j][q] = 0.f;

    const int NT = CIN / KC;   // 8
    float4 sa[8], sv[7];

#pragma unroll
    for (int i = 0; i < 8; i++) {
        int u = tid + 256 * i; int m = u >> 4; int k4 = (u & 15) * 4;
        sa[i] = *(const float4*)&W[(size_t)m * CIN + k4];
    }
#pragma unroll
    for (int i = 0; i < 7; i++) {
        int u = tid + 256 * i; int k = u / 28; int n4 = (u - k * 28) * 4;
        sv[i] = *(const float4*)&sb[(size_t)k * Pn + n0 + n4];
    }

#pragma unroll 1
    for (int t = 0; t < NT; t++) {
        const int buf = t & 1;
        {
            __nv_bfloat16* aHi = smb + buf * STG_E;
            __nv_bfloat16* aLo = aHi + A_E;
            __nv_bfloat16* bHi = aLo + A_E;
            __nv_bfloat16* bLo = bHi + B_E;
#pragma unroll
            for (int i = 0; i < 8; i++) {
                int u = tid + 256 * i; int m = u >> 4; int k4 = (u & 15) * 4;
                __nv_bfloat16 h0,h1,h2,h3,l0,l1,l2,l3;
                split2(sa[i].x, h0, l0); split2(sa[i].y, h1, l1);
                split2(sa[i].z, h2, l2); split2(sa[i].w, h3, l3);
                *(uint2*)&aHi[m * SK + k4] = make_uint2(pk2(h0,h1), pk2(h2,h3));
                *(uint2*)&aLo[m * SK + k4] = make_uint2(pk2(l0,l1), pk2(l2,l3));
            }
#pragma unroll
            for (int i = 0; i < 7; i++) {
                int u = tid + 256 * i; int k = u / 28; int n4 = (u - k * 28) * 4;
                __nv_bfloat16 h0,h1,h2,h3,l0,l1,l2,l3;
                split2(sv[i].x, h0, l0); split2(sv[i].y, h1, l1);
                split2(sv[i].z, h2, l2); split2(sv[i].w, h3, l3);
                *(uint2*)&bHi[k * SN + n4] = make_uint2(pk2(h0,h1), pk2(h2,h3));
                *(uint2*)&bLo[k * SN + n4] = make_uint2(pk2(l0,l1), pk2(l2,l3));
            }
        }
        if (t + 1 < NT) {
#pragma unroll
            for (int i = 0; i < 8; i++) {
                int u = tid + 256 * i; int m = u >> 4; int k4 = (u & 15) * 4;
                sa[i] = *(const float4*)&W[(size_t)m * CIN + (t + 1) * KC + k4];
            }
#pragma unroll
            for (int i = 0; i < 7; i++) {
                int u = tid + 256 * i; int k = u / 28; int n4 = (u - k * 28) * 4;
                sv[i] = *(const float4*)&sb[(size_t)((t + 1) * KC + k) * Pn + n0 + n4];
            }
        }
        __syncthreads();
        uint32_t aHiB = sbase + buf * STG_E * 2;
        mma_chunk(acc, aHiB, aHiB + 2 * AEb, lane, warp_m, warp_n);
    }

    // epilogue: BN + ReLU -> g_out1 (f32)
    const int r0 = lane >> 2, c0 = (lane & 3) * 2;
#pragma unroll
    for (int i = 0; i < 2; i++) {
        const int mA = warp_m + i * 16 + r0;
        const int mB = mA + 8;
        const float scA = scale[mA], biA = bias[mA];
        const float scB = scale[mB], biB = bias[mB];
        float* dA = g_out1 + ((size_t)b * CMID + mA) * Pn;
        float* dB = g_out1 + ((size_t)b * CMID + mB) * Pn;
#pragma unroll
        for (int j = 0; j < 7; j++) {
            const int n = n0 + warp_n + j * 8 + c0;
            float2 vA = {fmaxf(acc[i][j][0] * scA + biA, 0.f),
                         fmaxf(acc[i][j][1] * scA + biA, 0.f)};
            float2 vB = {fmaxf(acc[i][j][2] * scB + biB, 0.f),
                         fmaxf(acc[i][j][3] * scB + biB, 0.f)};
            *(float2*)&dA[n] = vA;
            *(float2*)&dB[n] = vB;
        }
    }
}

// ============================================================================
// conv3: 128->512, BN + residual. Operands pre-split bf16 -> pure cp.async.
// grid (7, 16, 4), 256 thr, 2 CTAs/SM, NT=2.
// ============================================================================
#define CONV3_SMEM (STG_E * 2)   // 67584 B

__global__ __launch_bounds__(256, 2) void k_conv3mm(const float* __restrict__ scale,
                                                    const float* __restrict__ bias,
                                                    const float* __restrict__ x,
                                                    float* __restrict__ out) {
    extern __shared__ __align__(16) __nv_bfloat16 smb[];
    const int tid = threadIdx.x, wid = tid >> 5, lane = tid & 31;
    const int b = blockIdx.y, n0 = blockIdx.x * BN, mo = blockIdx.z * BM;
    const int warp_m = (wid >> 1) * 32, warp_n = (wid & 1) * 56;
    const uint32_t aHiB = smem_u32(smb);
    const uint32_t bHiB = aHiB + 2 * AEb;

    float acc[2][7][4];
#pragma unroll
    for (int i = 0; i < 2; i++)
#pragma unroll
        for (int j = 0; j < 7; j++)
#pragma unroll
            for (int q = 0; q < 4; q++) acc[i][j][q] = 0.f;

#pragma unroll 1
    for (int t = 0; t < 2; t++) {
        if (t) __syncthreads();
        // A: 2 planes x 128 rows x 8 chunks (16B = 8 elems) = 2048
#pragma unroll
        for (int i = 0; i < 8; i++) {
            int q = tid + 256 * i;
            int plane = q >> 10, m = (q >> 3) & 127, j = q & 7;
            uint32_t dst = aHiB + (uint32_t)plane * AEb + (uint32_t)(m * SK + j * 8) * 2;
            const __nv_bfloat16* wp = plane ? g_w3l : g_w3h;
            cpa16(dst, wp + (size_t)(mo + m) * CMID + t * KC + j * 8);
        }
        // B: 2 planes x 64 rows x 14 chunks = 1792
#pragma unroll
        for (int i = 0; i < 7; i++) {
            int q = tid + 256 * i;
            int plane = q >= 896;
            int r = plane ? q - 896 : q;
            int k = r / 14, j = r - k * 14;
            uint32_t dst = bHiB + (uint32_t)plane * BEb + (uint32_t)(k * SN + j * 8) * 2;
            const __nv_bfloat16* op = plane ? g_o2l : g_o2h;
            cpa16(dst, op + ((size_t)b * CMID + t * KC + k) * Pn + n0 + j * 8);
        }
        CP_COMMIT();
        CP_WAIT0();
        __syncthreads();
        mma_chunk(acc, aHiB, bHiB, lane, warp_m, warp_n);
    }

    // epilogue: BN + residual -> out (f32)
    const int r0 = lane >> 2, c0 = (lane & 3) * 2;
#pragma unroll
    for (int i = 0; i < 2; i++) {
        const int mA = mo + warp_m + i * 16 + r0;
        const int mB = mA + 8;
        const float scA = scale[mA], biA = bias[mA];
        const float scB = scale[mB], biB = bias[mB];
        float* dA = out + ((size_t)b * CIN + mA) * Pn;
        float* dB = out + ((size_t)b * CIN + mB) * Pn;
        const float* rA = x + ((size_t)b * CIN + mA) * Pn;
        const float* rB = x + ((size_t)b * CIN + mB) * Pn;
#pragma unroll
        for (int j = 0; j < 7; j++) {
            const int n = n0 + warp_n + j * 8 + c0;
            float2 qA = *(const float2*)&rA[n];
            float2 qB = *(const float2*)&rB[n];
            float2 vA = {acc[i][j][0] * scA + biA + qA.x,
                         acc[i][j][1] * scA + biA + qA.y};
            float2 vB = {acc[i][j][2] * scB + biB + qB.x,
                         acc[i][j][3] * scB + biB + qB.y};
            *(float2*)&dA[n] = vA;
            *(float2*)&dB[n] = vB;
        }
    }
}

// ---------------------------------------------------------------------------
// W3 pre-split: f32 -> bf16 hi/lo
// ---------------------------------------------------------------------------
__global__ void k_splitw(const float* __restrict__ src) {
    int i = blockIdx.x * 256 + threadIdx.x;
    if (i < CIN * CMID) {
        __nv_bfloat16 h, l;
        split2(src[i], h, l);
        g_w3h[i] = h;
        g_w3l[i] = l;
    }
}

// ---------------------------------------------------------------------------
// Kernel 2: involution kernel generation — register-tiled (unchanged)
// ---------------------------------------------------------------------------
#define WRT_S 36

__global__ __launch_bounds__(256) void k_kgen(const float* __restrict__ Wr,
                                              const float* __restrict__ sr,
                                              const float* __restrict__ br,
                                              const float* __restrict__ Ws,
                                              const float* __restrict__ bs) {
    extern __shared__ float smk[];
    float* t1   = smk;
    float* WrT  = t1 + 16384;
    float* rshT = WrT + 128 * WRT_S;
    float* WsT  = rshT + 4096;

    const int b = blockIdx.y, n0 = blockIdx.x * 128, tid = threadIdx.x;
    const float* o1 = g_out1 + b * CMID * Pn;

#pragma unroll
    for (int i = 0; i < 16; i++) {
        int j = tid + 256 * i;
        int c = j >> 5, n4 = (j & 31) * 4;
        int n = n0 + n4;
        *(float4*)&t1[c * 128 + n4] =
            (n < Pn) ? *(const float4*)&o1[c * Pn + n] : make_float4(0.f,0.f,0.f,0.f);
    }
#pragma unroll
    for (int i = 0; i < 16; i++) {
        int j = tid + 256 * i;
        int m = j >> 7, c = j & 127;
        WrT[c * WRT_S + m] = Wr[j];
    }
#pragma unroll
    for (int i = 0; i < 49; i++) {
        int j = tid + 256 * i;
        int m = j >> 5, k = j & 31;
        WsT[k * 392 + m] = Ws[j];
    }
    __syncthreads();

    {
        const int mt = tid >> 5;
        const int nn = (tid & 31) * 4;
        float racc[4][4];
#pragma unroll
        for (int i = 0; i < 4; i++)
#pragma unroll
            for (int j = 0; j < 4; j++) racc[i][j] = 0.f;
#pragma unroll 8
        for (int c = 0; c < 128; c++) {
            float4 av = *(const float4*)&WrT[c * WRT_S + mt * 4];
            float4 bv = *(const float4*)&t1[c * 128 + nn];
            float ar[4] = {av.x, av.y, av.z, av.w};
            float bc[4] = {bv.x, bv.y, bv.z, bv.w};
#pragma unroll
            for (int i = 0; i < 4; i++)
#pragma unroll
                for (int j = 0; j < 4; j++) racc[i][j] += ar[i] * bc[j];
        }
#pragma unroll
        for (int i = 0; i < 4; i++) {
            int m = mt * 4 + i;
            float s = sr[m], bb = br[m];
            float4 v;
            v.x = fmaxf(racc[i][0]*s+bb, 0.f);
            v.y = fmaxf(racc[i][1]*s+bb, 0.f);
            v.z = fmaxf(racc[i][2]*s+bb, 0.f);
            v.w = fmaxf(racc[i][3]*s+bb, 0.f);
            *(float4*)&rshT[m * 128 + nn] = v;
        }
    }
    __syncthreads();

#pragma unroll 1
    for (int it = 0; it < 4; it++) {
        int unit = tid + 256 * it;
        if (unit >= 784) break;
        int mt = unit >> 4, nn = (unit & 15) * 8;
        float acc[8][8];
#pragma unroll
        for (int i = 0; i < 8; i++) {
            float bv = bs[mt * 8 + i];
#pragma unroll
            for (int j = 0; j < 8; j++) acc[i][j] = bv;
        }
#pragma unroll 8
        for (int k = 0; k < 32; k++) {
            float4 a0 = *(const float4*)&WsT[k * 392 + mt * 8];
            float4 a1 = *(const float4*)&WsT[k * 392 + mt * 8 + 4];
            float4 b0 = *(const float4*)&rshT[k * 128 + nn];
            float4 b1 = *(const float4*)&rshT[k * 128 + nn + 4];
            float ar[8] = {a0.x,a0.y,a0.z,a0.w,a1.x,a1.y,a1.z,a1.w};
            float bc[8] = {b0.x,b0.y,b0.z,b0.w,b1.x,b1.y,b1.z,b1.w};
#pragma unroll
            for (int i = 0; i < 8; i++)
#pragma unroll
                for (int j = 0; j < 8; j++) acc[i][j] += ar[i] * bc[j];
        }
        if (n0 + nn < Pn) {
#pragma unroll
            for (int i = 0; i < 8; i++) {
                int m = mt * 8 + i;
                float* wrow = g_w + (b * CSPAN + m) * Pn + n0 + nn;
                float4 v0 = {acc[i][0], acc[i][1], acc[i][2], acc[i][3]};
                float4 v1 = {acc[i][4], acc[i][5], acc[i][6], acc[i][7]};
                *(float4*)&wrow[0] = v0;
                *(float4*)&wrow[4] = v1;
            }
        }
    }
}

// ---------------------------------------------------------------------------
// Kernel 3: involution apply — now emits split-bf16 g_o2h / g_o2l
// ---------------------------------------------------------------------------
#define APL_SLOT 20
#define APL_SMEM (20 * 34 * APL_SLOT * 4)

__global__ __launch_bounds__(256) void k_apply() {
    extern __shared__ __align__(16) float xs[];
    const int y0 = blockIdx.x * 14;
    const int g  = blockIdx.y;
    const int b  = blockIdx.z;
    const int tid = threadIdx.x;

    const float* o1 = g_out1 + (b * CMID + g * 16) * Pn;
    for (int j = tid; j < 20 * 34 * 16; j += 256) {
        int c    = j & 15;
        int slot = j >> 4;
        int xx = slot % 34, yy = slot / 34;
        int gy = y0 + yy - 3, gx = xx - 3;
        float v = 0.f;
        if (gy >= 0 && gy < 28 && gx >= 0 && gx < 28)
            v = o1[c * Pn + gy * 28 + gx];
        xs[slot * APL_SLOT + c] = v;
    }
    __syncthreads();

    for (int idx = tid; idx < 14 * 28; idx += 256) {
        int y = idx / 28, xc = idx % 28;
        int hw = (y0 + y) * 28 + xc;
        const float* wp = g_w + (b * CSPAN + g * KK) * Pn + hw;
        float av[16];
#pragma unroll
        for (int c = 0; c < 16; c++) av[c] = 0.f;
#pragma unroll
        for (int k = 0; k < KK; k++) {
            float wk = wp[k * Pn];
            int dy = k / 7, dx = k % 7;
            const float* base = &xs[((y + dy) * 34 + xc + dx) * APL_SLOT];
            float4 v0 = *(const float4*)&base[0];
            float4 v1 = *(const float4*)&base[4];
            float4 v2 = *(const float4*)&base[8];
            float4 v3 = *(const float4*)&base[12];
            av[0] += wk*v0.x; av[1] += wk*v0.y; av[2] += wk*v0.z; av[3] += wk*v0.w;
            av[4] += wk*v1.x; av[5] += wk*v1.y; av[6] += wk*v1.z; av[7] += wk*v1.w;
            av[8] += wk*v2.x; av[9] += wk*v2.y; av[10]+= wk*v2.z; av[11]+= wk*v2.w;
            av[12]+= wk*v3.x; av[13]+= wk*v3.y; av[14]+= wk*v3.z; av[15]+= wk*v3.w;
        }
        size_t base = (size_t)(b * CMID + g * 16) * Pn + hw;
#pragma unroll
        for (int c = 0; c < 16; c++) {
            __nv_bfloat16 h, l;
            split2(av[c], h, l);
            g_o2h[base + (size_t)c * Pn] = h;
            g_o2l[base + (size_t)c * Pn] = l;
        }
    }
}

// ---------------------------------------------------------------------------
extern "C" void kernel_launch(void* const* d_in, const int* in_sizes, int n_in,
                              void* d_out, int out_size) {
    const float* x  = (const float*)d_in[0];
    const float* W1 = (const float*)d_in[1];
    const float* s1 = (const float*)d_in[2];
    const float* b1 = (const float*)d_in[3];
    const float* Wr = (const float*)d_in[4];
    const float* sr = (const float*)d_in[5];
    const float* br = (const float*)d_in[6];
    const float* Ws = (const float*)d_in[7];
    const float* bs = (const float*)d_in[8];
    const float* W3 = (const float*)d_in[9];
    const float* s3 = (const float*)d_in[10];
    const float* b3 = (const float*)d_in[11];
    float* out = (float*)d_out;

    const int kgen_smem = (16384 + 128 * WRT_S + 4096 + 12544) * 4;
    cudaFuncSetAttribute(k_kgen, cudaFuncAttributeMaxDynamicSharedMemorySize, kgen_smem);
    cudaFuncSetAttribute(k_apply, cudaFuncAttributeMaxDynamicSharedMemorySize, APL_SMEM);
    cudaFuncSetAttribute(k_conv1mm, cudaFuncAttributeMaxDynamicSharedMemorySize, CONV1_SMEM);
    cudaFuncSetAttribute(k_conv3mm, cudaFuncAttributeMaxDynamicSharedMemorySize, CONV3_SMEM);

    // W3 pre-split (independent of everything else)
    k_splitw<<<(CIN * CMID + 255) / 256, 256>>>(W3);
    // conv1: 512 -> 128, BN+ReLU
    k_conv1mm<<<dim3(7, 16), 256, CONV1_SMEM>>>(W1, s1, b1, x);
    // involution kernel generation
    k_kgen<<<dim3(7, 16), 256, kgen_smem>>>(Wr, sr, br, Ws, bs);
    // involution apply (emits split-bf16 o2)
    k_apply<<<dim3(2, NG, BATCH), 256, APL_SMEM>>>();
    // conv3: 128 -> 512, BN + residual
    k_conv3mm<<<dim3(7, 16, 4), 256, CONV3_SMEM>>>(s3, b3, x, out);
}

// round 6
// speedup vs baseline: 3.0032x; 1.0003x over previous
#include <cuda_runtime.h>
#include <cuda_bf16.h>
#include <cstdint>

#define Pn    784
#define BATCH 16
#define CIN   512
#define CMID  128
#define CRED  32
#define NG    8
#define KK    49
#define CSPAN 392   // KK * NG

// Scratch (device globals: allocation-free rule)
__device__ float g_out1[BATCH * CMID * Pn];                 // 6.4 MB
__device__ float g_w[BATCH * CSPAN * Pn];                   // 19.7 MB
__device__ __nv_bfloat16 g_o2h[BATCH * CMID * Pn];          // 3.2 MB
__device__ __nv_bfloat16 g_o2l[BATCH * CMID * Pn];          // 3.2 MB
__device__ __nv_bfloat16 g_w3h[CIN * CMID];
__device__ __nv_bfloat16 g_w3l[CIN * CMID];

// ============================================================================
// helpers
// ============================================================================
__device__ __forceinline__ uint32_t smem_u32(const void* p) {
    uint32_t a;
    asm("{ .reg .u64 t; cvta.to.shared.u64 t, %1; cvt.u32.u64 %0, t; }"
        : "=r"(a) : "l"(p));
    return a;
}
__device__ __forceinline__ void mma_bf16(float* d, const uint32_t* a, const uint32_t* b) {
    asm volatile(
        "mma.sync.aligned.m16n8k16.row.col.f32.bf16.bf16.f32 "
        "{%0,%1,%2,%3}, {%4,%5,%6,%7}, {%8,%9}, {%0,%1,%2,%3};"
        : "+f"(d[0]), "+f"(d[1]), "+f"(d[2]), "+f"(d[3])
        : "r"(a[0]), "r"(a[1]), "r"(a[2]), "r"(a[3]), "r"(b[0]), "r"(b[1]));
}
__device__ __forceinline__ void ldsm_x4(uint32_t* r, uint32_t a) {
    asm volatile("ldmatrix.sync.aligned.m8n8.x4.shared.b16 {%0,%1,%2,%3}, [%4];"
        : "=r"(r[0]), "=r"(r[1]), "=r"(r[2]), "=r"(r[3]) : "r"(a));
}
__device__ __forceinline__ void ldsm_x4_t(uint32_t* r, uint32_t a) {
    asm volatile("ldmatrix.sync.aligned.m8n8.x4.trans.shared.b16 {%0,%1,%2,%3}, [%4];"
        : "=r"(r[0]), "=r"(r[1]), "=r"(r[2]), "=r"(r[3]) : "r"(a));
}
__device__ __forceinline__ void ldsm_x2_t(uint32_t* r, uint32_t a) {
    asm volatile("ldmatrix.sync.aligned.m8n8.x2.trans.shared.b16 {%0,%1}, [%2];"
        : "=r"(r[0]), "=r"(r[1]) : "r"(a));
}
__device__ __forceinline__ void cpa16(uint32_t dst, const void* src) {
    asm volatile("cp.async.ca.shared.global [%0], [%1], 16;" :: "r"(dst), "l"(src));
}
#define CP_COMMIT() asm volatile("cp.async.commit_group;" ::: "memory")
#define CP_WAIT0()  asm volatile("cp.async.wait_group 0;" ::: "memory")

__device__ __forceinline__ void split2(float f, __nv_bfloat16& h, __nv_bfloat16& l) {
    h = __float2bfloat16(f);
    l = __float2bfloat16(f - __bfloat162float(h));
}
__device__ __forceinline__ uint32_t pk2(__nv_bfloat16 a, __nv_bfloat16 b) {
    __nv_bfloat162 t = __halves2bfloat162(a, b);
    return *reinterpret_cast<uint32_t*>(&t);
}

// ============================================================================
// Shared GEMM tile geometry. A [128m][SK k] row-major, B [KC k][SN n] row-major
// (consumed via ldmatrix.trans). Split-bf16 3-term accumulation.
// ============================================================================
#define BM 128
#define BN 112
#define KC 64
#define SK 72
#define SN 120
#define A_E (BM * SK)
#define B_E (KC * SN)
#define STG_E (2 * A_E + 2 * B_E)
#define AEb (A_E * 2)
#define BEb (B_E * 2)

__device__ __forceinline__ void mma_chunk(float (&acc)[2][7][4],
                                          uint32_t aHiB, uint32_t bHiB,
                                          int lane, int warp_m, int warp_n) {
    const int l15 = lane & 15, l7 = lane & 7;
    const uint32_t aRow = (uint32_t)(warp_m + l15) * SK + ((lane >> 4) & 1) * 8;
#pragma unroll
    for (int ks = 0; ks < 4; ks++) {
        uint32_t ah[2][4], al[2][4];
#pragma unroll
        for (int i = 0; i < 2; i++) {
            uint32_t ad = aHiB + (aRow + (uint32_t)(i * 16 * SK + ks * 16)) * 2;
            ldsm_x4(ah[i], ad);
            ldsm_x4(al[i], ad + AEb);
        }
#pragma unroll
        for (int jp = 0; jp < 3; jp++) {
            uint32_t kr = (uint32_t)(ks * 16 + l7 + ((lane >> 3) & 1) * 8);
            uint32_t nc = (uint32_t)(warp_n + jp * 16 + (lane >> 4) * 8);
            uint32_t bd = bHiB + (kr * SN + nc) * 2;
            uint32_t rh[4], rl[4];
            ldsm_x4_t(rh, bd);
            ldsm_x4_t(rl, bd + BEb);
#pragma unroll
            for (int i = 0; i < 2; i++) {
                mma_bf16(acc[i][2*jp],   ah[i], rh + 0);
                mma_bf16(acc[i][2*jp],   ah[i], rl + 0);
                mma_bf16(acc[i][2*jp],   al[i], rh + 0);
                mma_bf16(acc[i][2*jp+1], ah[i], rh + 2);
                mma_bf16(acc[i][2*jp+1], ah[i], rl + 2);
                mma_bf16(acc[i][2*jp+1], al[i], rh + 2);
            }
        }
        {
            uint32_t kr = (uint32_t)(ks * 16 + l15);
            uint32_t bd = bHiB + (kr * SN + (uint32_t)(warp_n + 48)) * 2;
            uint32_t rh[2], rl[2];
            ldsm_x2_t(rh, bd);
            ldsm_x2_t(rl, bd + BEb);
#pragma unroll
            for (int i = 0; i < 2; i++) {
                mma_bf16(acc[i][6], ah[i], rh);
                mma_bf16(acc[i][6], ah[i], rl);
                mma_bf16(acc[i][6], al[i], rh);
            }
        }
    }
}

// ============================================================================
// conv1: 512->128, BN+ReLU. fp32 in-kernel split, double-buffered, reg-staged.
// ============================================================================
#define CONV1_SMEM (2 * STG_E * 2)

__global__ __launch_bounds__(256) void k_conv1mm(const float* __restrict__ W,
                                                 const float* __restrict__ scale,
                                                 const float* __restrict__ bias,
                                                 const float* __restrict__ x) {
    extern __shared__ __align__(16) __nv_bfloat16 smb[];
    const int tid = threadIdx.x, wid = tid >> 5, lane = tid & 31;
    const int b = blockIdx.y, n0 = blockIdx.x * BN;
    const int warp_m = (wid >> 1) * 32, warp_n = (wid & 1) * 56;
    const float* sb = x + (size_t)b * CIN * Pn;
    const uint32_t sbase = smem_u32(smb);

    float acc[2][7][4];
#pragma unroll
    for (int i = 0; i < 2; i++)
#pragma unroll
        for (int j = 0; j < 7; j++)
#pragma unroll
            for (int q = 0; q < 4; q++) acc[i][j][q] = 0.f;

    const int NT = CIN / KC;
    float4 sa[8], sv[7];

#pragma unroll
    for (int i = 0; i < 8; i++) {
        int u = tid + 256 * i; int m = u >> 4; int k4 = (u & 15) * 4;
        sa[i] = *(const float4*)&W[(size_t)m * CIN + k4];
    }
#pragma unroll
    for (int i = 0; i < 7; i++) {
        int u = tid + 256 * i; int k = u / 28; int n4 = (u - k * 28) * 4;
        sv[i] = *(const float4*)&sb[(size_t)k * Pn + n0 + n4];
    }

#pragma unroll 1
    for (int t = 0; t < NT; t++) {
        const int buf = t & 1;
        {
            __nv_bfloat16* aHi = smb + buf * STG_E;
            __nv_bfloat16* aLo = aHi + A_E;
            __nv_bfloat16* bHi = aLo + A_E;
            __nv_bfloat16* bLo = bHi + B_E;
#pragma unroll
            for (int i = 0; i < 8; i++) {
                int u = tid + 256 * i; int m = u >> 4; int k4 = (u & 15) * 4;
                __nv_bfloat16 h0,h1,h2,h3,l0,l1,l2,l3;
                split2(sa[i].x, h0, l0); split2(sa[i].y, h1, l1);
                split2(sa[i].z, h2, l2); split2(sa[i].w, h3, l3);
                *(uint2*)&aHi[m * SK + k4] = make_uint2(pk2(h0,h1), pk2(h2,h3));
                *(uint2*)&aLo[m * SK + k4] = make_uint2(pk2(l0,l1), pk2(l2,l3));
            }
#pragma unroll
            for (int i = 0; i < 7; i++) {
                int u = tid + 256 * i; int k = u / 28; int n4 = (u - k * 28) * 4;
                __nv_bfloat16 h0,h1,h2,h3,l0,l1,l2,l3;
                split2(sv[i].x, h0, l0); split2(sv[i].y, h1, l1);
                split2(sv[i].z, h2, l2); split2(sv[i].w, h3, l3);
                *(uint2*)&bHi[k * SN + n4] = make_uint2(pk2(h0,h1), pk2(h2,h3));
                *(uint2*)&bLo[k * SN + n4] = make_uint2(pk2(l0,l1), pk2(l2,l3));
            }
        }
        if (t + 1 < NT) {
#pragma unroll
            for (int i = 0; i < 8; i++) {
                int u = tid + 256 * i; int m = u >> 4; int k4 = (u & 15) * 4;
                sa[i] = *(const float4*)&W[(size_t)m * CIN + (t + 1) * KC + k4];
            }
#pragma unroll
            for (int i = 0; i < 7; i++) {
                int u = tid + 256 * i; int k = u / 28; int n4 = (u - k * 28) * 4;
                sv[i] = *(const float4*)&sb[(size_t)((t + 1) * KC + k) * Pn + n0 + n4];
            }
        }
        __syncthreads();
        uint32_t aHiB = sbase + buf * STG_E * 2;
        mma_chunk(acc, aHiB, aHiB + 2 * AEb, lane, warp_m, warp_n);
    }

    const int r0 = lane >> 2, c0 = (lane & 3) * 2;
#pragma unroll
    for (int i = 0; i < 2; i++) {
        const int mA = warp_m + i * 16 + r0;
        const int mB = mA + 8;
        const float scA = scale[mA], biA = bias[mA];
        const float scB = scale[mB], biB = bias[mB];
        float* dA = g_out1 + ((size_t)b * CMID + mA) * Pn;
        float* dB = g_out1 + ((size_t)b * CMID + mB) * Pn;
#pragma unroll
        for (int j = 0; j < 7; j++) {
            const int n = n0 + warp_n + j * 8 + c0;
            float2 vA = {fmaxf(acc[i][j][0] * scA + biA, 0.f),
                         fmaxf(acc[i][j][1] * scA + biA, 0.f)};
            float2 vB = {fmaxf(acc[i][j][2] * scB + biB, 0.f),
                         fmaxf(acc[i][j][3] * scB + biB, 0.f)};
            *(float2*)&dA[n] = vA;
            *(float2*)&dB[n] = vB;
        }
    }
}

// ============================================================================
// conv3: 128->512, BN + residual. Pre-split operands, pure cp.async, 2 CTAs/SM.
// ============================================================================
#define CONV3_SMEM (STG_E * 2)

__global__ __launch_bounds__(256, 2) void k_conv3mm(const float* __restrict__ scale,
                                                    const float* __restrict__ bias,
                                                    const float* __restrict__ x,
                                                    float* __restrict__ out) {
    extern __shared__ __align__(16) __nv_bfloat16 smb[];
    const int tid = threadIdx.x, wid = tid >> 5, lane = tid & 31;
    const int b = blockIdx.y, n0 = blockIdx.x * BN, mo = blockIdx.z * BM;
    const int warp_m = (wid >> 1) * 32, warp_n = (wid & 1) * 56;
    const uint32_t aHiB = smem_u32(smb);
    const uint32_t bHiB = aHiB + 2 * AEb;

    float acc[2][7][4];
#pragma unroll
    for (int i = 0; i < 2; i++)
#pragma unroll
        for (int j = 0; j < 7; j++)
#pragma unroll
            for (int q = 0; q < 4; q++) acc[i][j][q] = 0.f;

#pragma unroll 1
    for (int t = 0; t < 2; t++) {
        if (t) __syncthreads();
#pragma unroll
        for (int i = 0; i < 8; i++) {
            int q = tid + 256 * i;
            int plane = q >> 10, m = (q >> 3) & 127, j = q & 7;
            uint32_t dst = aHiB + (uint32_t)plane * AEb + (uint32_t)(m * SK + j * 8) * 2;
            const __nv_bfloat16* wp = plane ? g_w3l : g_w3h;
            cpa16(dst, wp + (size_t)(mo + m) * CMID + t * KC + j * 8);
        }
#pragma unroll
        for (int i = 0; i < 7; i++) {
            int q = tid + 256 * i;
            int plane = q >= 896;
            int r = plane ? q - 896 : q;
            int k = r / 14, j = r - k * 14;
            uint32_t dst = bHiB + (uint32_t)plane * BEb + (uint32_t)(k * SN + j * 8) * 2;
            const __nv_bfloat16* op = plane ? g_o2l : g_o2h;
            cpa16(dst, op + ((size_t)b * CMID + t * KC + k) * Pn + n0 + j * 8);
        }
        CP_COMMIT();
        CP_WAIT0();
        __syncthreads();
        mma_chunk(acc, aHiB, bHiB, lane, warp_m, warp_n);
    }

    const int r0 = lane >> 2, c0 = (lane & 3) * 2;
#pragma unroll
    for (int i = 0; i < 2; i++) {
        const int mA = mo + warp_m + i * 16 + r0;
        const int mB = mA + 8;
        const float scA = scale[mA], biA = bias[mA];
        const float scB = scale[mB], biB = bias[mB];
        float* dA = out + ((size_t)b * CIN + mA) * Pn;
        float* dB = out + ((size_t)b * CIN + mB) * Pn;
        const float* rA = x + ((size_t)b * CIN + mA) * Pn;
        const float* rB = x + ((size_t)b * CIN + mB) * Pn;
#pragma unroll
        for (int j = 0; j < 7; j++) {
            const int n = n0 + warp_n + j * 8 + c0;
            float2 qA = *(const float2*)&rA[n];
            float2 qB = *(const float2*)&rB[n];
            float2 vA = {acc[i][j][0] * scA + biA + qA.x,
                         acc[i][j][1] * scA + biA + qA.y};
            float2 vB = {acc[i][j][2] * scB + biB + qB.x,
                         acc[i][j][3] * scB + biB + qB.y};
            *(float2*)&dA[n] = vA;
            *(float2*)&dB[n] = vB;
        }
    }
}

// ---------------------------------------------------------------------------
// W3 pre-split: f32 -> bf16 hi/lo
// ---------------------------------------------------------------------------
__global__ void k_splitw(const float* __restrict__ src) {
    int i = blockIdx.x * 256 + threadIdx.x;
    if (i < CIN * CMID) {
        __nv_bfloat16 h, l;
        split2(src[i], h, l);
        g_w3h[i] = h;
        g_w3l[i] = l;
    }
}

// ---------------------------------------------------------------------------
// Kernel 2: involution kernel generation — register-tiled (unchanged)
// ---------------------------------------------------------------------------
#define WRT_S 36

__global__ __launch_bounds__(256) void k_kgen(const float* __restrict__ Wr,
                                              const float* __restrict__ sr,
                                              const float* __restrict__ br,
                                              const float* __restrict__ Ws,
                                              const float* __restrict__ bs) {
    extern __shared__ float smk[];
    float* t1   = smk;
    float* WrT  = t1 + 16384;
    float* rshT = WrT + 128 * WRT_S;
    float* WsT  = rshT + 4096;

    const int b = blockIdx.y, n0 = blockIdx.x * 128, tid = threadIdx.x;
    const float* o1 = g_out1 + b * CMID * Pn;

#pragma unroll
    for (int i = 0; i < 16; i++) {
        int j = tid + 256 * i;
        int c = j >> 5, n4 = (j & 31) * 4;
        int n = n0 + n4;
        *(float4*)&t1[c * 128 + n4] =
            (n < Pn) ? *(const float4*)&o1[c * Pn + n] : make_float4(0.f,0.f,0.f,0.f);
    }
#pragma unroll
    for (int i = 0; i < 16; i++) {
        int j = tid + 256 * i;
        int m = j >> 7, c = j & 127;
        WrT[c * WRT_S + m] = Wr[j];
    }
#pragma unroll
    for (int i = 0; i < 49; i++) {
        int j = tid + 256 * i;
        int m = j >> 5, k = j & 31;
        WsT[k * 392 + m] = Ws[j];
    }
    __syncthreads();

    {
        const int mt = tid >> 5;
        const int nn = (tid & 31) * 4;
        float racc[4][4];
#pragma unroll
        for (int i = 0; i < 4; i++)
#pragma unroll
            for (int j = 0; j < 4; j++) racc[i][j] = 0.f;
#pragma unroll 8
        for (int c = 0; c < 128; c++) {
            float4 av = *(const float4*)&WrT[c * WRT_S + mt * 4];
            float4 bv = *(const float4*)&t1[c * 128 + nn];
            float ar[4] = {av.x, av.y, av.z, av.w};
            float bc[4] = {bv.x, bv.y, bv.z, bv.w};
#pragma unroll
            for (int i = 0; i < 4; i++)
#pragma unroll
                for (int j = 0; j < 4; j++) racc[i][j] += ar[i] * bc[j];
        }
#pragma unroll
        for (int i = 0; i < 4; i++) {
            int m = mt * 4 + i;
            float s = sr[m], bb = br[m];
            float4 v;
            v.x = fmaxf(racc[i][0]*s+bb, 0.f);
            v.y = fmaxf(racc[i][1]*s+bb, 0.f);
            v.z = fmaxf(racc[i][2]*s+bb, 0.f);
            v.w = fmaxf(racc[i][3]*s+bb, 0.f);
            *(float4*)&rshT[m * 128 + nn] = v;
        }
    }
    __syncthreads();

#pragma unroll 1
    for (int it = 0; it < 4; it++) {
        int unit = tid + 256 * it;
        if (unit >= 784) break;
        int mt = unit >> 4, nn = (unit & 15) * 8;
        float acc[8][8];
#pragma unroll
        for (int i = 0; i < 8; i++) {
            float bv = bs[mt * 8 + i];
#pragma unroll
            for (int j = 0; j < 8; j++) acc[i][j] = bv;
        }
#pragma unroll 8
        for (int k = 0; k < 32; k++) {
            float4 a0 = *(const float4*)&WsT[k * 392 + mt * 8];
            float4 a1 = *(const float4*)&WsT[k * 392 + mt * 8 + 4];
            float4 b0 = *(const float4*)&rshT[k * 128 + nn];
            float4 b1 = *(const float4*)&rshT[k * 128 + nn + 4];
            float ar[8] = {a0.x,a0.y,a0.z,a0.w,a1.x,a1.y,a1.z,a1.w};
            float bc[8] = {b0.x,b0.y,b0.z,b0.w,b1.x,b1.y,b1.z,b1.w};
#pragma unroll
            for (int i = 0; i < 8; i++)
#pragma unroll
                for (int j = 0; j < 8; j++) acc[i][j] += ar[i] * bc[j];
        }
        if (n0 + nn < Pn) {
#pragma unroll
            for (int i = 0; i < 8; i++) {
                int m = mt * 8 + i;
                float* wrow = g_w + (b * CSPAN + m) * Pn + n0 + nn;
                float4 v0 = {acc[i][0], acc[i][1], acc[i][2], acc[i][3]};
                float4 v1 = {acc[i][4], acc[i][5], acc[i][6], acc[i][7]};
                *(float4*)&wrow[0] = v0;
                *(float4*)&wrow[4] = v1;
            }
        }
    }
}

// ---------------------------------------------------------------------------
// Kernel 3: involution apply — quarter-height blocks, register-preloaded weights
// grid (4 y-chunks, 8 groups, 16 batch) = 512 blocks, 256 threads.
// Tile: 13 rows x 34 cols x 16 ch, slot stride 20 floats (35.4 KB).
// ---------------------------------------------------------------------------
#define APL_SLOT 20
#define APL_R    13
#define APL_SMEM (APL_R * 34 * APL_SLOT * 4)   // 35,360 B

__global__ __launch_bounds__(256, 3) void k_apply() {
    extern __shared__ __align__(16) float xs[];
    const int y0 = blockIdx.x * 7;
    const int g  = blockIdx.y;
    const int b  = blockIdx.z;
    const int tid = threadIdx.x;

    const float* o1 = g_out1 + (b * CMID + g * 16) * Pn;
    for (int j = tid; j < APL_R * 34 * 16; j += 256) {
        int c    = j & 15;
        int slot = j >> 4;
        int xx = slot % 34, yy = slot / 34;
        int gy = y0 + yy - 3, gx = xx - 3;
        float v = 0.f;
        if (gy >= 0 && gy < 28 && gx >= 0 && gx < 28)
            v = o1[c * Pn + gy * 28 + gx];
        xs[slot * APL_SLOT + c] = v;
    }
    __syncthreads();

    if (tid < 196) {
        const int y = tid / 28, xc = tid % 28;
        const int hw = (y0 + y) * 28 + xc;
        const float* wp = g_w + (b * CSPAN + g * KK) * Pn + hw;
        float av[16];
#pragma unroll
        for (int c = 0; c < 16; c++) av[c] = 0.f;

        // weights preloaded in 2 chunks (25 + 24) for high MLP
#pragma unroll
        for (int ch = 0; ch < 2; ch++) {
            const int k0 = ch * 25;
            const int cnt = ch ? 24 : 25;
            float w[25];
#pragma unroll
            for (int kk = 0; kk < 25; kk++) {
                if (kk < cnt) w[kk] = wp[(size_t)(k0 + kk) * Pn];
            }
#pragma unroll
            for (int kk = 0; kk < 25; kk++) {
                if (kk >= cnt) break;
                const int k = k0 + kk;
                const int dy = k / 7, dx = k % 7;
                const float wk = w[kk];
                const float* base = &xs[((y + dy) * 34 + xc + dx) * APL_SLOT];
                float4 v0 = *(const float4*)&base[0];
                float4 v1 = *(const float4*)&base[4];
                float4 v2 = *(const float4*)&base[8];
                float4 v3 = *(const float4*)&base[12];
                av[0] += wk*v0.x; av[1] += wk*v0.y; av[2] += wk*v0.z; av[3] += wk*v0.w;
                av[4] += wk*v1.x; av[5] += wk*v1.y; av[6] += wk*v1.z; av[7] += wk*v1.w;
                av[8] += wk*v2.x; av[9] += wk*v2.y; av[10]+= wk*v2.z; av[11]+= wk*v2.w;
                av[12]+= wk*v3.x; av[13]+= wk*v3.y; av[14]+= wk*v3.z; av[15]+= wk*v3.w;
            }
        }

        size_t base = (size_t)(b * CMID + g * 16) * Pn + hw;
#pragma unroll
        for (int c = 0; c < 16; c++) {
            __nv_bfloat16 h, l;
            split2(av[c], h, l);
            g_o2h[base + (size_t)c * Pn] = h;
            g_o2l[base + (size_t)c * Pn] = l;
        }
    }
}

// ---------------------------------------------------------------------------
extern "C" void kernel_launch(void* const* d_in, const int* in_sizes, int n_in,
                              void* d_out, int out_size) {
    const float* x  = (const float*)d_in[0];
    const float* W1 = (const float*)d_in[1];
    const float* s1 = (const float*)d_in[2];
    const float* b1 = (const float*)d_in[3];
    const float* Wr = (const float*)d_in[4];
    const float* sr = (const float*)d_in[5];
    const float* br = (const float*)d_in[6];
    const float* Ws = (const float*)d_in[7];
    const float* bs = (const float*)d_in[8];
    const float* W3 = (const float*)d_in[9];
    const float* s3 = (const float*)d_in[10];
    const float* b3 = (const float*)d_in[11];
    float* out = (float*)d_out;

    const int kgen_smem = (16384 + 128 * WRT_S + 4096 + 12544) * 4;
    cudaFuncSetAttribute(k_kgen, cudaFuncAttributeMaxDynamicSharedMemorySize, kgen_smem);
    cudaFuncSetAttribute(k_apply, cudaFuncAttributeMaxDynamicSharedMemorySize, APL_SMEM);
    cudaFuncSetAttribute(k_conv1mm, cudaFuncAttributeMaxDynamicSharedMemorySize, CONV1_SMEM);
    cudaFuncSetAttribute(k_conv3mm, cudaFuncAttributeMaxDynamicSharedMemorySize, CONV3_SMEM);

    // W3 pre-split (independent of everything else)
    k_splitw<<<(CIN * CMID + 255) / 256, 256>>>(W3);
    // conv1: 512 -> 128, BN+ReLU
    k_conv1mm<<<dim3(7, 16), 256, CONV1_SMEM>>>(W1, s1, b1, x);
    // involution kernel generation
    k_kgen<<<dim3(7, 16), 256, kgen_smem>>>(Wr, sr, br, Ws, bs);
    // involution apply (emits split-bf16 o2)
    k_apply<<<dim3(4, NG, BATCH), 256, APL_SMEM>>>();
    // conv3: 128 -> 512, BN + residual
    k_conv3mm<<<dim3(7, 16, 4), 256, CONV3_SMEM>>>(s3, b3, x, out);
}

// round 7
// speedup vs baseline: 3.1487x; 1.0485x over previous
#include <cuda_runtime.h>
#include <cuda_bf16.h>
#include <cstdint>

#define Pn    784
#define BATCH 16
#define CIN   512
#define CMID  128
#define CRED  32
#define NG    8
#define KK    49
#define CSPAN 392   // KK * NG

// Scratch (device globals: allocation-free rule)
__device__ float g_out1[BATCH * CMID * Pn];                 // 6.4 MB
__device__ float g_w[BATCH * CSPAN * Pn];                   // 19.7 MB
__device__ __nv_bfloat16 g_o2h[BATCH * CMID * Pn];          // 3.2 MB
__device__ __nv_bfloat16 g_o2l[BATCH * CMID * Pn];          // 3.2 MB
__device__ __nv_bfloat16 g_w3h[CIN * CMID];
__device__ __nv_bfloat16 g_w3l[CIN * CMID];

// ============================================================================
// helpers
// ============================================================================
__device__ __forceinline__ uint32_t smem_u32(const void* p) {
    uint32_t a;
    asm("{ .reg .u64 t; cvta.to.shared.u64 t, %1; cvt.u32.u64 %0, t; }"
        : "=r"(a) : "l"(p));
    return a;
}
__device__ __forceinline__ void mma_bf16(float* d, const uint32_t* a, const uint32_t* b) {
    asm volatile(
        "mma.sync.aligned.m16n8k16.row.col.f32.bf16.bf16.f32 "
        "{%0,%1,%2,%3}, {%4,%5,%6,%7}, {%8,%9}, {%0,%1,%2,%3};"
        : "+f"(d[0]), "+f"(d[1]), "+f"(d[2]), "+f"(d[3])
        : "r"(a[0]), "r"(a[1]), "r"(a[2]), "r"(a[3]), "r"(b[0]), "r"(b[1]));
}
__device__ __forceinline__ void ldsm_x4(uint32_t* r, uint32_t a) {
    asm volatile("ldmatrix.sync.aligned.m8n8.x4.shared.b16 {%0,%1,%2,%3}, [%4];"
        : "=r"(r[0]), "=r"(r[1]), "=r"(r[2]), "=r"(r[3]) : "r"(a));
}
__device__ __forceinline__ void ldsm_x4_t(uint32_t* r, uint32_t a) {
    asm volatile("ldmatrix.sync.aligned.m8n8.x4.trans.shared.b16 {%0,%1,%2,%3}, [%4];"
        : "=r"(r[0]), "=r"(r[1]), "=r"(r[2]), "=r"(r[3]) : "r"(a));
}
__device__ __forceinline__ void ldsm_x2_t(uint32_t* r, uint32_t a) {
    asm volatile("ldmatrix.sync.aligned.m8n8.x2.trans.shared.b16 {%0,%1}, [%2];"
        : "=r"(r[0]), "=r"(r[1]) : "r"(a));
}
__device__ __forceinline__ void cpa16(uint32_t dst, const void* src) {
    asm volatile("cp.async.ca.shared.global [%0], [%1], 16;" :: "r"(dst), "l"(src));
}
#define CP_COMMIT() asm volatile("cp.async.commit_group;" ::: "memory")
#define CP_WAIT0()  asm volatile("cp.async.wait_group 0;" ::: "memory")

__device__ __forceinline__ void split2(float f, __nv_bfloat16& h, __nv_bfloat16& l) {
    h = __float2bfloat16(f);
    l = __float2bfloat16(f - __bfloat162float(h));
}
__device__ __forceinline__ uint32_t pk2(__nv_bfloat16 a, __nv_bfloat16 b) {
    __nv_bfloat162 t = __halves2bfloat162(a, b);
    return *reinterpret_cast<uint32_t*>(&t);
}

// ============================================================================
// Shared GEMM tile geometry. A [128m][SK k] row-major, B [KC k][SN n] row-major
// (consumed via ldmatrix.trans). Split-bf16 3-term accumulation.
// ============================================================================
#define BM 128
#define BN 112
#define KC 64
#define SK 72
#define SN 120
#define A_E (BM * SK)
#define B_E (KC * SN)
#define STG_E (2 * A_E + 2 * B_E)
#define AEb (A_E * 2)
#define BEb (B_E * 2)

__device__ __forceinline__ void mma_chunk(float (&acc)[2][7][4],
                                          uint32_t aHiB, uint32_t bHiB,
                                          int lane, int warp_m, int warp_n) {
    const int l15 = lane & 15, l7 = lane & 7;
    const uint32_t aRow = (uint32_t)(warp_m + l15) * SK + ((lane >> 4) & 1) * 8;
#pragma unroll
    for (int ks = 0; ks < 4; ks++) {
        uint32_t ah[2][4], al[2][4];
#pragma unroll
        for (int i = 0; i < 2; i++) {
            uint32_t ad = aHiB + (aRow + (uint32_t)(i * 16 * SK + ks * 16)) * 2;
            ldsm_x4(ah[i], ad);
            ldsm_x4(al[i], ad + AEb);
        }
#pragma unroll
        for (int jp = 0; jp < 3; jp++) {
            uint32_t kr = (uint32_t)(ks * 16 + l7 + ((lane >> 3) & 1) * 8);
            uint32_t nc = (uint32_t)(warp_n + jp * 16 + (lane >> 4) * 8);
            uint32_t bd = bHiB + (kr * SN + nc) * 2;
            uint32_t rh[4], rl[4];
            ldsm_x4_t(rh, bd);
            ldsm_x4_t(rl, bd + BEb);
#pragma unroll
            for (int i = 0; i < 2; i++) {
                mma_bf16(acc[i][2*jp],   ah[i], rh + 0);
                mma_bf16(acc[i][2*jp],   ah[i], rl + 0);
                mma_bf16(acc[i][2*jp],   al[i], rh + 0);
                mma_bf16(acc[i][2*jp+1], ah[i], rh + 2);
                mma_bf16(acc[i][2*jp+1], ah[i], rl + 2);
                mma_bf16(acc[i][2*jp+1], al[i], rh + 2);
            }
        }
        {
            uint32_t kr = (uint32_t)(ks * 16 + l15);
            uint32_t bd = bHiB + (kr * SN + (uint32_t)(warp_n + 48)) * 2;
            uint32_t rh[2], rl[2];
            ldsm_x2_t(rh, bd);
            ldsm_x2_t(rl, bd + BEb);
#pragma unroll
            for (int i = 0; i < 2; i++) {
                mma_bf16(acc[i][6], ah[i], rh);
                mma_bf16(acc[i][6], ah[i], rl);
                mma_bf16(acc[i][6], al[i], rh);
            }
        }
    }
}

// ============================================================================
// conv1: 512->128, BN+ReLU. fp32 in-kernel split, double-buffered, reg-staged.
// ============================================================================
#define CONV1_SMEM (2 * STG_E * 2)

__global__ __launch_bounds__(256) void k_conv1mm(const float* __restrict__ W,
                                                 const float* __restrict__ scale,
                                                 const float* __restrict__ bias,
                                                 const float* __restrict__ x) {
    extern __shared__ __align__(16) __nv_bfloat16 smb[];
    const int tid = threadIdx.x, wid = tid >> 5, lane = tid & 31;
    const int b = blockIdx.y, n0 = blockIdx.x * BN;
    const int warp_m = (wid >> 1) * 32, warp_n = (wid & 1) * 56;
    const float* sb = x + (size_t)b * CIN * Pn;
    const uint32_t sbase = smem_u32(smb);

    float acc[2][7][4];
#pragma unroll
    for (int i = 0; i < 2; i++)
#pragma unroll
        for (int j = 0; j < 7; j++)
#pragma unroll
            for (int q = 0; q < 4; q++) acc[i][j][q] = 0.f;

    const int NT = CIN / KC;
    float4 sa[8], sv[7];

#pragma unroll
    for (int i = 0; i < 8; i++) {
        int u = tid + 256 * i; int m = u >> 4; int k4 = (u & 15) * 4;
        sa[i] = *(const float4*)&W[(size_t)m * CIN + k4];
    }
#pragma unroll
    for (int i = 0; i < 7; i++) {
        int u = tid + 256 * i; int k = u / 28; int n4 = (u - k * 28) * 4;
        sv[i] = *(const float4*)&sb[(size_t)k * Pn + n0 + n4];
    }

#pragma unroll 1
    for (int t = 0; t < NT; t++) {
        const int buf = t & 1;
        {
            __nv_bfloat16* aHi = smb + buf * STG_E;
            __nv_bfloat16* aLo = aHi + A_E;
            __nv_bfloat16* bHi = aLo + A_E;
            __nv_bfloat16* bLo = bHi + B_E;
#pragma unroll
            for (int i = 0; i < 8; i++) {
                int u = tid + 256 * i; int m = u >> 4; int k4 = (u & 15) * 4;
                __nv_bfloat16 h0,h1,h2,h3,l0,l1,l2,l3;
                split2(sa[i].x, h0, l0); split2(sa[i].y, h1, l1);
                split2(sa[i].z, h2, l2); split2(sa[i].w, h3, l3);
                *(uint2*)&aHi[m * SK + k4] = make_uint2(pk2(h0,h1), pk2(h2,h3));
                *(uint2*)&aLo[m * SK + k4] = make_uint2(pk2(l0,l1), pk2(l2,l3));
            }
#pragma unroll
            for (int i = 0; i < 7; i++) {
                int u = tid + 256 * i; int k = u / 28; int n4 = (u - k * 28) * 4;
                __nv_bfloat16 h0,h1,h2,h3,l0,l1,l2,l3;
                split2(sv[i].x, h0, l0); split2(sv[i].y, h1, l1);
                split2(sv[i].z, h2, l2); split2(sv[i].w, h3, l3);
                *(uint2*)&bHi[k * SN + n4] = make_uint2(pk2(h0,h1), pk2(h2,h3));
                *(uint2*)&bLo[k * SN + n4] = make_uint2(pk2(l0,l1), pk2(l2,l3));
            }
        }
        if (t + 1 < NT) {
#pragma unroll
            for (int i = 0; i < 8; i++) {
                int u = tid + 256 * i; int m = u >> 4; int k4 = (u & 15) * 4;
                sa[i] = *(const float4*)&W[(size_t)m * CIN + (t + 1) * KC + k4];
            }
#pragma unroll
            for (int i = 0; i < 7; i++) {
                int u = tid + 256 * i; int k = u / 28; int n4 = (u - k * 28) * 4;
                sv[i] = *(const float4*)&sb[(size_t)((t + 1) * KC + k) * Pn + n0 + n4];
            }
        }
        __syncthreads();
        uint32_t aHiB = sbase + buf * STG_E * 2;
        mma_chunk(acc, aHiB, aHiB + 2 * AEb, lane, warp_m, warp_n);
    }

    const int r0 = lane >> 2, c0 = (lane & 3) * 2;
#pragma unroll
    for (int i = 0; i < 2; i++) {
        const int mA = warp_m + i * 16 + r0;
        const int mB = mA + 8;
        const float scA = scale[mA], biA = bias[mA];
        const float scB = scale[mB], biB = bias[mB];
        float* dA = g_out1 + ((size_t)b * CMID + mA) * Pn;
        float* dB = g_out1 + ((size_t)b * CMID + mB) * Pn;
#pragma unroll
        for (int j = 0; j < 7; j++) {
            const int n = n0 + warp_n + j * 8 + c0;
            float2 vA = {fmaxf(acc[i][j][0] * scA + biA, 0.f),
                         fmaxf(acc[i][j][1] * scA + biA, 0.f)};
            float2 vB = {fmaxf(acc[i][j][2] * scB + biB, 0.f),
                         fmaxf(acc[i][j][3] * scB + biB, 0.f)};
            *(float2*)&dA[n] = vA;
            *(float2*)&dB[n] = vB;
        }
    }
}

// ============================================================================
// conv3: 128->512, BN + residual. Pre-split operands, pure cp.async, 2 CTAs/SM.
// ============================================================================
#define CONV3_SMEM (STG_E * 2)

__global__ __launch_bounds__(256, 2) void k_conv3mm(const float* __restrict__ scale,
                                                    const float* __restrict__ bias,
                                                    const float* __restrict__ x,
                                                    float* __restrict__ out) {
    extern __shared__ __align__(16) __nv_bfloat16 smb[];
    const int tid = threadIdx.x, wid = tid >> 5, lane = tid & 31;
    const int b = blockIdx.y, n0 = blockIdx.x * BN, mo = blockIdx.z * BM;
    const int warp_m = (wid >> 1) * 32, warp_n = (wid & 1) * 56;
    const uint32_t aHiB = smem_u32(smb);
    const uint32_t bHiB = aHiB + 2 * AEb;

    float acc[2][7][4];
#pragma unroll
    for (int i = 0; i < 2; i++)
#pragma unroll
        for (int j = 0; j < 7; j++)
#pragma unroll
            for (int q = 0; q < 4; q++) acc[i][j][q] = 0.f;

#pragma unroll 1
    for (int t = 0; t < 2; t++) {
        if (t) __syncthreads();
#pragma unroll
        for (int i = 0; i < 8; i++) {
            int q = tid + 256 * i;
            int plane = q >> 10, m = (q >> 3) & 127, j = q & 7;
            uint32_t dst = aHiB + (uint32_t)plane * AEb + (uint32_t)(m * SK + j * 8) * 2;
            const __nv_bfloat16* wp = plane ? g_w3l : g_w3h;
            cpa16(dst, wp + (size_t)(mo + m) * CMID + t * KC + j * 8);
        }
#pragma unroll
        for (int i = 0; i < 7; i++) {
            int q = tid + 256 * i;
            int plane = q >= 896;
            int r = plane ? q - 896 : q;
            int k = r / 14, j = r - k * 14;
            uint32_t dst = bHiB + (uint32_t)plane * BEb + (uint32_t)(k * SN + j * 8) * 2;
            const __nv_bfloat16* op = plane ? g_o2l : g_o2h;
            cpa16(dst, op + ((size_t)b * CMID + t * KC + k) * Pn + n0 + j * 8);
        }
        CP_COMMIT();
        CP_WAIT0();
        __syncthreads();
        mma_chunk(acc, aHiB, bHiB, lane, warp_m, warp_n);
    }

    const int r0 = lane >> 2, c0 = (lane & 3) * 2;
#pragma unroll
    for (int i = 0; i < 2; i++) {
        const int mA = mo + warp_m + i * 16 + r0;
        const int mB = mA + 8;
        const float scA = scale[mA], biA = bias[mA];
        const float scB = scale[mB], biB = bias[mB];
        float* dA = out + ((size_t)b * CIN + mA) * Pn;
        float* dB = out + ((size_t)b * CIN + mB) * Pn;
        const float* rA = x + ((size_t)b * CIN + mA) * Pn;
        const float* rB = x + ((size_t)b * CIN + mB) * Pn;
#pragma unroll
        for (int j = 0; j < 7; j++) {
            const int n = n0 + warp_n + j * 8 + c0;
            float2 qA = *(const float2*)&rA[n];
            float2 qB = *(const float2*)&rB[n];
            float2 vA = {acc[i][j][0] * scA + biA + qA.x,
                         acc[i][j][1] * scA + biA + qA.y};
            float2 vB = {acc[i][j][2] * scB + biB + qB.x,
                         acc[i][j][3] * scB + biB + qB.y};
            *(float2*)&dA[n] = vA;
            *(float2*)&dB[n] = vB;
        }
    }
}

// ---------------------------------------------------------------------------
// W3 pre-split: f32 -> bf16 hi/lo
// ---------------------------------------------------------------------------
__global__ void k_splitw(const float* __restrict__ src) {
    int i = blockIdx.x * 256 + threadIdx.x;
    if (i < CIN * CMID) {
        __nv_bfloat16 h, l;
        split2(src[i], h, l);
        g_w3h[i] = h;
        g_w3l[i] = l;
    }
}

// ---------------------------------------------------------------------------
// Kernel 2: involution kernel generation — register-tiled (unchanged)
// ---------------------------------------------------------------------------
#define WRT_S 36

__global__ __launch_bounds__(256) void k_kgen(const float* __restrict__ Wr,
                                              const float* __restrict__ sr,
                                              const float* __restrict__ br,
                                              const float* __restrict__ Ws,
                                              const float* __restrict__ bs) {
    extern __shared__ float smk[];
    float* t1   = smk;
    float* WrT  = t1 + 16384;
    float* rshT = WrT + 128 * WRT_S;
    float* WsT  = rshT + 4096;

    const int b = blockIdx.y, n0 = blockIdx.x * 128, tid = threadIdx.x;
    const float* o1 = g_out1 + b * CMID * Pn;

#pragma unroll
    for (int i = 0; i < 16; i++) {
        int j = tid + 256 * i;
        int c = j >> 5, n4 = (j & 31) * 4;
        int n = n0 + n4;
        *(float4*)&t1[c * 128 + n4] =
            (n < Pn) ? *(const float4*)&o1[c * Pn + n] : make_float4(0.f,0.f,0.f,0.f);
    }
#pragma unroll
    for (int i = 0; i < 16; i++) {
        int j = tid + 256 * i;
        int m = j >> 7, c = j & 127;
        WrT[c * WRT_S + m] = Wr[j];
    }
#pragma unroll
    for (int i = 0; i < 49; i++) {
        int j = tid + 256 * i;
        int m = j >> 5, k = j & 31;
        WsT[k * 392 + m] = Ws[j];
    }
    __syncthreads();

    {
        const int mt = tid >> 5;
        const int nn = (tid & 31) * 4;
        float racc[4][4];
#pragma unroll
        for (int i = 0; i < 4; i++)
#pragma unroll
            for (int j = 0; j < 4; j++) racc[i][j] = 0.f;
#pragma unroll 8
        for (int c = 0; c < 128; c++) {
            float4 av = *(const float4*)&WrT[c * WRT_S + mt * 4];
            float4 bv = *(const float4*)&t1[c * 128 + nn];
            float ar[4] = {av.x, av.y, av.z, av.w};
            float bc[4] = {bv.x, bv.y, bv.z, bv.w};
#pragma unroll
            for (int i = 0; i < 4; i++)
#pragma unroll
                for (int j = 0; j < 4; j++) racc[i][j] += ar[i] * bc[j];
        }
#pragma unroll
        for (int i = 0; i < 4; i++) {
            int m = mt * 4 + i;
            float s = sr[m], bb = br[m];
            float4 v;
            v.x = fmaxf(racc[i][0]*s+bb, 0.f);
            v.y = fmaxf(racc[i][1]*s+bb, 0.f);
            v.z = fmaxf(racc[i][2]*s+bb, 0.f);
            v.w = fmaxf(racc[i][3]*s+bb, 0.f);
            *(float4*)&rshT[m * 128 + nn] = v;
        }
    }
    __syncthreads();

#pragma unroll 1
    for (int it = 0; it < 4; it++) {
        int unit = tid + 256 * it;
        if (unit >= 784) break;
        int mt = unit >> 4, nn = (unit & 15) * 8;
        float acc[8][8];
#pragma unroll
        for (int i = 0; i < 8; i++) {
            float bv = bs[mt * 8 + i];
#pragma unroll
            for (int j = 0; j < 8; j++) acc[i][j] = bv;
        }
#pragma unroll 8
        for (int k = 0; k < 32; k++) {
            float4 a0 = *(const float4*)&WsT[k * 392 + mt * 8];
            float4 a1 = *(const float4*)&WsT[k * 392 + mt * 8 + 4];
            float4 b0 = *(const float4*)&rshT[k * 128 + nn];
            float4 b1 = *(const float4*)&rshT[k * 128 + nn + 4];
            float ar[8] = {a0.x,a0.y,a0.z,a0.w,a1.x,a1.y,a1.z,a1.w};
            float bc[8] = {b0.x,b0.y,b0.z,b0.w,b1.x,b1.y,b1.z,b1.w};
#pragma unroll
            for (int i = 0; i < 8; i++)
#pragma unroll
                for (int j = 0; j < 8; j++) acc[i][j] += ar[i] * bc[j];
        }
        if (n0 + nn < Pn) {
#pragma unroll
            for (int i = 0; i < 8; i++) {
                int m = mt * 8 + i;
                float* wrow = g_w + (b * CSPAN + m) * Pn + n0 + nn;
                float4 v0 = {acc[i][0], acc[i][1], acc[i][2], acc[i][3]};
                float4 v1 = {acc[i][4], acc[i][5], acc[i][6], acc[i][7]};
                *(float4*)&wrow[0] = v0;
                *(float4*)&wrow[4] = v1;
            }
        }
    }
}

// ---------------------------------------------------------------------------
// Kernel 3: involution apply — vertical pixel-pairing (y, y+1) per thread.
// Tap sharing: slot (y+i) serves row y (dy=i, i<7) and row y+1 (dy=i-1, i>=1)
// -> 8 slot-loads feed 14 tap-applies: 1.75x fewer LDS.128 than per-pixel.
// grid (2 half-planes, 8 groups, 16 batch) = 256 blocks, 196/256 threads live.
// Tile: 20 rows x 34 cols x 16 ch, slot stride 20 floats (54.4 KB, 2 CTAs/SM).
// ---------------------------------------------------------------------------
#define APL_SLOT 20
#define APL_R    20
#define APL_SMEM (APL_R * 34 * APL_SLOT * 4)   // 54,400 B

__global__ __launch_bounds__(256, 2) void k_apply() {
    extern __shared__ __align__(16) float xs[];
    const int y0 = blockIdx.x * 14;
    const int g  = blockIdx.y;
    const int b  = blockIdx.z;
    const int tid = threadIdx.x;

    const float* o1 = g_out1 + (b * CMID + g * 16) * Pn;
    for (int j = tid; j < APL_R * 34 * 16; j += 256) {
        int c    = j & 15;
        int slot = j >> 4;
        int xx = slot % 34, yy = slot / 34;
        int gy = y0 + yy - 3, gx = xx - 3;
        float v = 0.f;
        if (gy >= 0 && gy < 28 && gx >= 0 && gx < 28)
            v = o1[c * Pn + gy * 28 + gx];
        xs[slot * APL_SLOT + c] = v;
    }
    __syncthreads();

    if (tid < 196) {
        const int yA = (tid / 28) * 2;          // local output row (even)
        const int xc = tid % 28;
        const int hwA = (y0 + yA) * 28 + xc;
        const int hwB = hwA + 28;
        const float* wbase = g_w + ((size_t)b * CSPAN + (size_t)g * KK) * Pn;

        float accA[16], accB[16];
#pragma unroll
        for (int c = 0; c < 16; c++) { accA[c] = 0.f; accB[c] = 0.f; }

#pragma unroll
        for (int dx = 0; dx < 7; dx++) {
            // preload this dx-column's weights for both rows (14 LDG in flight)
            float wA[7], wB[7];
#pragma unroll
            for (int dy = 0; dy < 7; dy++) {
                const size_t wo = (size_t)(dy * 7 + dx) * Pn;
                wA[dy] = wbase[wo + hwA];
                wB[dy] = wbase[wo + hwB];
            }
#pragma unroll
            for (int i = 0; i < 8; i++) {
                const float* base = &xs[((yA + i) * 34 + xc + dx) * APL_SLOT];
                float4 v0 = *(const float4*)&base[0];
                float4 v1 = *(const float4*)&base[4];
                float4 v2 = *(const float4*)&base[8];
                float4 v3 = *(const float4*)&base[12];
                if (i < 7) {
                    const float w = wA[i];
                    accA[0] += w*v0.x; accA[1] += w*v0.y; accA[2] += w*v0.z; accA[3] += w*v0.w;
                    accA[4] += w*v1.x; accA[5] += w*v1.y; accA[6] += w*v1.z; accA[7] += w*v1.w;
                    accA[8] += w*v2.x; accA[9] += w*v2.y; accA[10]+= w*v2.z; accA[11]+= w*v2.w;
                    accA[12]+= w*v3.x; accA[13]+= w*v3.y; accA[14]+= w*v3.z; accA[15]+= w*v3.w;
                }
                if (i >= 1) {
                    const float w = wB[i - 1];
                    accB[0] += w*v0.x; accB[1] += w*v0.y; accB[2] += w*v0.z; accB[3] += w*v0.w;
                    accB[4] += w*v1.x; accB[5] += w*v1.y; accB[6] += w*v1.z; accB[7] += w*v1.w;
                    accB[8] += w*v2.x; accB[9] += w*v2.y; accB[10]+= w*v2.z; accB[11]+= w*v2.w;
                    accB[12]+= w*v3.x; accB[13]+= w*v3.y; accB[14]+= w*v3.z; accB[15]+= w*v3.w;
                }
            }
        }

        const size_t baseA = (size_t)(b * CMID + g * 16) * Pn + hwA;
#pragma unroll
        for (int c = 0; c < 16; c++) {
            __nv_bfloat16 h, l;
            split2(accA[c], h, l);
            g_o2h[baseA + (size_t)c * Pn] = h;
            g_o2l[baseA + (size_t)c * Pn] = l;
        }
#pragma unroll
        for (int c = 0; c < 16; c++) {
            __nv_bfloat16 h, l;
            split2(accB[c], h, l);
            g_o2h[baseA + 28 + (size_t)c * Pn] = h;
            g_o2l[baseA + 28 + (size_t)c * Pn] = l;
        }
    }
}

// ---------------------------------------------------------------------------
extern "C" void kernel_launch(void* const* d_in, const int* in_sizes, int n_in,
                              void* d_out, int out_size) {
    const float* x  = (const float*)d_in[0];
    const float* W1 = (const float*)d_in[1];
    const float* s1 = (const float*)d_in[2];
    const float* b1 = (const float*)d_in[3];
    const float* Wr = (const float*)d_in[4];
    const float* sr = (const float*)d_in[5];
    const float* br = (const float*)d_in[6];
    const float* Ws = (const float*)d_in[7];
    const float* bs = (const float*)d_in[8];
    const float* W3 = (const float*)d_in[9];
    const float* s3 = (const float*)d_in[10];
    const float* b3 = (const float*)d_in[11];
    float* out = (float*)d_out;

    const int kgen_smem = (16384 + 128 * WRT_S + 4096 + 12544) * 4;
    cudaFuncSetAttribute(k_kgen, cudaFuncAttributeMaxDynamicSharedMemorySize, kgen_smem);
    cudaFuncSetAttribute(k_apply, cudaFuncAttributeMaxDynamicSharedMemorySize, APL_SMEM);
    cudaFuncSetAttribute(k_conv1mm, cudaFuncAttributeMaxDynamicSharedMemorySize, CONV1_SMEM);
    cudaFuncSetAttribute(k_conv3mm, cudaFuncAttributeMaxDynamicSharedMemorySize, CONV3_SMEM);

    // W3 pre-split (independent of everything else)
    k_splitw<<<(CIN * CMID + 255) / 256, 256>>>(W3);
    // conv1: 512 -> 128, BN+ReLU
    k_conv1mm<<<dim3(7, 16), 256, CONV1_SMEM>>>(W1, s1, b1, x);
    // involution kernel generation
    k_kgen<<<dim3(7, 16), 256, kgen_smem>>>(Wr, sr, br, Ws, bs);
    // involution apply (emits split-bf16 o2)
    k_apply<<<dim3(2, NG, BATCH), 256, APL_SMEM>>>();
    // conv3: 128 -> 512, BN + residual
    k_conv3mm<<<dim3(7, 16, 4), 256, CONV3_SMEM>>>(s3, b3, x, out);
}

// round 8
// speedup vs baseline: 3.1508x; 1.0007x over previous
#include <cuda_runtime.h>
#include <cuda_bf16.h>
#include <cstdint>

#define Pn    784
#define BATCH 16
#define CIN   512
#define CMID  128
#define CRED  32
#define NG    8
#define KK    49
#define CSPAN 392   // KK * NG

// Scratch (device globals: allocation-free rule)
__device__ float g_out1[BATCH * CMID * Pn];                 // 6.4 MB
__device__ float g_w[BATCH * CSPAN * Pn];                   // 19.7 MB
__device__ __nv_bfloat16 g_o2h[BATCH * CMID * Pn];          // 3.2 MB
__device__ __nv_bfloat16 g_o2l[BATCH * CMID * Pn];          // 3.2 MB
__device__ __nv_bfloat16 g_w3h[CIN * CMID];
__device__ __nv_bfloat16 g_w3l[CIN * CMID];

// ============================================================================
// helpers
// ============================================================================
__device__ __forceinline__ uint32_t smem_u32(const void* p) {
    uint32_t a;
    asm("{ .reg .u64 t; cvta.to.shared.u64 t, %1; cvt.u32.u64 %0, t; }"
        : "=r"(a) : "l"(p));
    return a;
}
__device__ __forceinline__ void mma_bf16(float* d, const uint32_t* a, const uint32_t* b) {
    asm volatile(
        "mma.sync.aligned.m16n8k16.row.col.f32.bf16.bf16.f32 "
        "{%0,%1,%2,%3}, {%4,%5,%6,%7}, {%8,%9}, {%0,%1,%2,%3};"
        : "+f"(d[0]), "+f"(d[1]), "+f"(d[2]), "+f"(d[3])
        : "r"(a[0]), "r"(a[1]), "r"(a[2]), "r"(a[3]), "r"(b[0]), "r"(b[1]));
}
__device__ __forceinline__ void ldsm_x4(uint32_t* r, uint32_t a) {
    asm volatile("ldmatrix.sync.aligned.m8n8.x4.shared.b16 {%0,%1,%2,%3}, [%4];"
        : "=r"(r[0]), "=r"(r[1]), "=r"(r[2]), "=r"(r[3]) : "r"(a));
}
__device__ __forceinline__ void ldsm_x4_t(uint32_t* r, uint32_t a) {
    asm volatile("ldmatrix.sync.aligned.m8n8.x4.trans.shared.b16 {%0,%1,%2,%3}, [%4];"
        : "=r"(r[0]), "=r"(r[1]), "=r"(r[2]), "=r"(r[3]) : "r"(a));
}
__device__ __forceinline__ void ldsm_x2_t(uint32_t* r, uint32_t a) {
    asm volatile("ldmatrix.sync.aligned.m8n8.x2.trans.shared.b16 {%0,%1}, [%2];"
        : "=r"(r[0]), "=r"(r[1]) : "r"(a));
}
__device__ __forceinline__ void cpa16(uint32_t dst, const void* src) {
    asm volatile("cp.async.ca.shared.global [%0], [%1], 16;" :: "r"(dst), "l"(src));
}
#define CP_COMMIT() asm volatile("cp.async.commit_group;" ::: "memory")
#define CP_WAIT0()  asm volatile("cp.async.wait_group 0;" ::: "memory")

__device__ __forceinline__ void split2(float f, __nv_bfloat16& h, __nv_bfloat16& l) {
    h = __float2bfloat16(f);
    l = __float2bfloat16(f - __bfloat162float(h));
}
__device__ __forceinline__ uint32_t pk2(__nv_bfloat16 a, __nv_bfloat16 b) {
    __nv_bfloat162 t = __halves2bfloat162(a, b);
    return *reinterpret_cast<uint32_t*>(&t);
}

// ============================================================================
// Shared GEMM tile geometry. A [128m][SK k] row-major, B [KC k][SN n] row-major
// (consumed via ldmatrix.trans). Split-bf16 3-term accumulation.
// ============================================================================
#define BM 128
#define BN 112
#define KC 64
#define SK 72
#define SN 120
#define A_E (BM * SK)
#define B_E (KC * SN)
#define STG_E (2 * A_E + 2 * B_E)
#define AEb (A_E * 2)
#define BEb (B_E * 2)

__device__ __forceinline__ void mma_chunk(float (&acc)[2][7][4],
                                          uint32_t aHiB, uint32_t bHiB,
                                          int lane, int warp_m, int warp_n) {
    const int l15 = lane & 15, l7 = lane & 7;
    const uint32_t aRow = (uint32_t)(warp_m + l15) * SK + ((lane >> 4) & 1) * 8;
#pragma unroll
    for (int ks = 0; ks < 4; ks++) {
        uint32_t ah[2][4], al[2][4];
#pragma unroll
        for (int i = 0; i < 2; i++) {
            uint32_t ad = aHiB + (aRow + (uint32_t)(i * 16 * SK + ks * 16)) * 2;
            ldsm_x4(ah[i], ad);
            ldsm_x4(al[i], ad + AEb);
        }
#pragma unroll
        for (int jp = 0; jp < 3; jp++) {
            uint32_t kr = (uint32_t)(ks * 16 + l7 + ((lane >> 3) & 1) * 8);
            uint32_t nc = (uint32_t)(warp_n + jp * 16 + (lane >> 4) * 8);
            uint32_t bd = bHiB + (kr * SN + nc) * 2;
            uint32_t rh[4], rl[4];
            ldsm_x4_t(rh, bd);
            ldsm_x4_t(rl, bd + BEb);
#pragma unroll
            for (int i = 0; i < 2; i++) {
                mma_bf16(acc[i][2*jp],   ah[i], rh + 0);
                mma_bf16(acc[i][2*jp],   ah[i], rl + 0);
                mma_bf16(acc[i][2*jp],   al[i], rh + 0);
                mma_bf16(acc[i][2*jp+1], ah[i], rh + 2);
                mma_bf16(acc[i][2*jp+1], ah[i], rl + 2);
                mma_bf16(acc[i][2*jp+1], al[i], rh + 2);
            }
        }
        {
            uint32_t kr = (uint32_t)(ks * 16 + l15);
            uint32_t bd = bHiB + (kr * SN + (uint32_t)(warp_n + 48)) * 2;
            uint32_t rh[2], rl[2];
            ldsm_x2_t(rh, bd);
            ldsm_x2_t(rl, bd + BEb);
#pragma unroll
            for (int i = 0; i < 2; i++) {
                mma_bf16(acc[i][6], ah[i], rh);
                mma_bf16(acc[i][6], ah[i], rl);
                mma_bf16(acc[i][6], al[i], rh);
            }
        }
    }
}

// ============================================================================
// conv1: 512->128, BN+ReLU. fp32 in-kernel split, double-buffered, reg-staged.
// ============================================================================
#define CONV1_SMEM (2 * STG_E * 2)

__global__ __launch_bounds__(256) void k_conv1mm(const float* __restrict__ W,
                                                 const float* __restrict__ scale,
                                                 const float* __restrict__ bias,
                                                 const float* __restrict__ x) {
    extern __shared__ __align__(16) __nv_bfloat16 smb[];
    const int tid = threadIdx.x, wid = tid >> 5, lane = tid & 31;
    const int b = blockIdx.y, n0 = blockIdx.x * BN;
    const int warp_m = (wid >> 1) * 32, warp_n = (wid & 1) * 56;
    const float* sb = x + (size_t)b * CIN * Pn;
    const uint32_t sbase = smem_u32(smb);

    float acc[2][7][4];
#pragma unroll
    for (int i = 0; i < 2; i++)
#pragma unroll
        for (int j = 0; j < 7; j++)
#pragma unroll
            for (int q = 0; q < 4; q++) acc[i][j][q] = 0.f;

    const int NT = CIN / KC;
    float4 sa[8], sv[7];

#pragma unroll
    for (int i = 0; i < 8; i++) {
        int u = tid + 256 * i; int m = u >> 4; int k4 = (u & 15) * 4;
        sa[i] = *(const float4*)&W[(size_t)m * CIN + k4];
    }
#pragma unroll
    for (int i = 0; i < 7; i++) {
        int u = tid + 256 * i; int k = u / 28; int n4 = (u - k * 28) * 4;
        sv[i] = *(const float4*)&sb[(size_t)k * Pn + n0 + n4];
    }

#pragma unroll 1
    for (int t = 0; t < NT; t++) {
        const int buf = t & 1;
        {
            __nv_bfloat16* aHi = smb + buf * STG_E;
            __nv_bfloat16* aLo = aHi + A_E;
            __nv_bfloat16* bHi = aLo + A_E;
            __nv_bfloat16* bLo = bHi + B_E;
#pragma unroll
            for (int i = 0; i < 8; i++) {
                int u = tid + 256 * i; int m = u >> 4; int k4 = (u & 15) * 4;
                __nv_bfloat16 h0,h1,h2,h3,l0,l1,l2,l3;
                split2(sa[i].x, h0, l0); split2(sa[i].y, h1, l1);
                split2(sa[i].z, h2, l2); split2(sa[i].w, h3, l3);
                *(uint2*)&aHi[m * SK + k4] = make_uint2(pk2(h0,h1), pk2(h2,h3));
                *(uint2*)&aLo[m * SK + k4] = make_uint2(pk2(l0,l1), pk2(l2,l3));
            }
#pragma unroll
            for (int i = 0; i < 7; i++) {
                int u = tid + 256 * i; int k = u / 28; int n4 = (u - k * 28) * 4;
                __nv_bfloat16 h0,h1,h2,h3,l0,l1,l2,l3;
                split2(sv[i].x, h0, l0); split2(sv[i].y, h1, l1);
                split2(sv[i].z, h2, l2); split2(sv[i].w, h3, l3);
                *(uint2*)&bHi[k * SN + n4] = make_uint2(pk2(h0,h1), pk2(h2,h3));
                *(uint2*)&bLo[k * SN + n4] = make_uint2(pk2(l0,l1), pk2(l2,l3));
            }
        }
        if (t + 1 < NT) {
#pragma unroll
            for (int i = 0; i < 8; i++) {
                int u = tid + 256 * i; int m = u >> 4; int k4 = (u & 15) * 4;
                sa[i] = *(const float4*)&W[(size_t)m * CIN + (t + 1) * KC + k4];
            }
#pragma unroll
            for (int i = 0; i < 7; i++) {
                int u = tid + 256 * i; int k = u / 28; int n4 = (u - k * 28) * 4;
                sv[i] = *(const float4*)&sb[(size_t)((t + 1) * KC + k) * Pn + n0 + n4];
            }
        }
        __syncthreads();
        uint32_t aHiB = sbase + buf * STG_E * 2;
        mma_chunk(acc, aHiB, aHiB + 2 * AEb, lane, warp_m, warp_n);
    }

    const int r0 = lane >> 2, c0 = (lane & 3) * 2;
#pragma unroll
    for (int i = 0; i < 2; i++) {
        const int mA = warp_m + i * 16 + r0;
        const int mB = mA + 8;
        const float scA = scale[mA], biA = bias[mA];
        const float scB = scale[mB], biB = bias[mB];
        float* dA = g_out1 + ((size_t)b * CMID + mA) * Pn;
        float* dB = g_out1 + ((size_t)b * CMID + mB) * Pn;
#pragma unroll
        for (int j = 0; j < 7; j++) {
            const int n = n0 + warp_n + j * 8 + c0;
            float2 vA = {fmaxf(acc[i][j][0] * scA + biA, 0.f),
                         fmaxf(acc[i][j][1] * scA + biA, 0.f)};
            float2 vB = {fmaxf(acc[i][j][2] * scB + biB, 0.f),
                         fmaxf(acc[i][j][3] * scB + biB, 0.f)};
            *(float2*)&dA[n] = vA;
            *(float2*)&dB[n] = vB;
        }
    }
}

// ============================================================================
// conv3: 128->512, BN + residual. Pre-split operands, pure cp.async, 2 CTAs/SM.
// ============================================================================
#define CONV3_SMEM (STG_E * 2)

__global__ __launch_bounds__(256, 2) void k_conv3mm(const float* __restrict__ scale,
                                                    const float* __restrict__ bias,
                                                    const float* __restrict__ x,
                                                    float* __restrict__ out) {
    extern __shared__ __align__(16) __nv_bfloat16 smb[];
    const int tid = threadIdx.x, wid = tid >> 5, lane = tid & 31;
    const int b = blockIdx.y, n0 = blockIdx.x * BN, mo = blockIdx.z * BM;
    const int warp_m = (wid >> 1) * 32, warp_n = (wid & 1) * 56;
    const uint32_t aHiB = smem_u32(smb);
    const uint32_t bHiB = aHiB + 2 * AEb;

    float acc[2][7][4];
#pragma unroll
    for (int i = 0; i < 2; i++)
#pragma unroll
        for (int j = 0; j < 7; j++)
#pragma unroll
            for (int q = 0; q < 4; q++) acc[i][j][q] = 0.f;

#pragma unroll 1
    for (int t = 0; t < 2; t++) {
        if (t) __syncthreads();
#pragma unroll
        for (int i = 0; i < 8; i++) {
            int q = tid + 256 * i;
            int plane = q >> 10, m = (q >> 3) & 127, j = q & 7;
            uint32_t dst = aHiB + (uint32_t)plane * AEb + (uint32_t)(m * SK + j * 8) * 2;
            const __nv_bfloat16* wp = plane ? g_w3l : g_w3h;
            cpa16(dst, wp + (size_t)(mo + m) * CMID + t * KC + j * 8);
        }
#pragma unroll
        for (int i = 0; i < 7; i++) {
            int q = tid + 256 * i;
            int plane = q >= 896;
            int r = plane ? q - 896 : q;
            int k = r / 14, j = r - k * 14;
            uint32_t dst = bHiB + (uint32_t)plane * BEb + (uint32_t)(k * SN + j * 8) * 2;
            const __nv_bfloat16* op = plane ? g_o2l : g_o2h;
            cpa16(dst, op + ((size_t)b * CMID + t * KC + k) * Pn + n0 + j * 8);
        }
        CP_COMMIT();
        CP_WAIT0();
        __syncthreads();
        mma_chunk(acc, aHiB, bHiB, lane, warp_m, warp_n);
    }

    const int r0 = lane >> 2, c0 = (lane & 3) * 2;
#pragma unroll
    for (int i = 0; i < 2; i++) {
        const int mA = mo + warp_m + i * 16 + r0;
        const int mB = mA + 8;
        const float scA = scale[mA], biA = bias[mA];
        const float scB = scale[mB], biB = bias[mB];
        float* dA = out + ((size_t)b * CIN + mA) * Pn;
        float* dB = out + ((size_t)b * CIN + mB) * Pn;
        const float* rA = x + ((size_t)b * CIN + mA) * Pn;
        const float* rB = x + ((size_t)b * CIN + mB) * Pn;
#pragma unroll
        for (int j = 0; j < 7; j++) {
            const int n = n0 + warp_n + j * 8 + c0;
            float2 qA = *(const float2*)&rA[n];
            float2 qB = *(const float2*)&rB[n];
            float2 vA = {acc[i][j][0] * scA + biA + qA.x,
                         acc[i][j][1] * scA + biA + qA.y};
            float2 vB = {acc[i][j][2] * scB + biB + qB.x,
                         acc[i][j][3] * scB + biB + qB.y};
            *(float2*)&dA[n] = vA;
            *(float2*)&dB[n] = vB;
        }
    }
}

// ---------------------------------------------------------------------------
// W3 pre-split: f32 -> bf16 hi/lo
// ---------------------------------------------------------------------------
__global__ void k_splitw(const float* __restrict__ src) {
    int i = blockIdx.x * 256 + threadIdx.x;
    if (i < CIN * CMID) {
        __nv_bfloat16 h, l;
        split2(src[i], h, l);
        g_w3h[i] = h;
        g_w3l[i] = l;
    }
}

// ---------------------------------------------------------------------------
// Kernel 2: involution kernel generation — register-tiled (unchanged)
// ---------------------------------------------------------------------------
#define WRT_S 36

__global__ __launch_bounds__(256) void k_kgen(const float* __restrict__ Wr,
                                              const float* __restrict__ sr,
                                              const float* __restrict__ br,
                                              const float* __restrict__ Ws,
                                              const float* __restrict__ bs) {
    extern __shared__ float smk[];
    float* t1   = smk;
    float* WrT  = t1 + 16384;
    float* rshT = WrT + 128 * WRT_S;
    float* WsT  = rshT + 4096;

    const int b = blockIdx.y, n0 = blockIdx.x * 128, tid = threadIdx.x;
    const float* o1 = g_out1 + b * CMID * Pn;

#pragma unroll
    for (int i = 0; i < 16; i++) {
        int j = tid + 256 * i;
        int c = j >> 5, n4 = (j & 31) * 4;
        int n = n0 + n4;
        *(float4*)&t1[c * 128 + n4] =
            (n < Pn) ? *(const float4*)&o1[c * Pn + n] : make_float4(0.f,0.f,0.f,0.f);
    }
#pragma unroll
    for (int i = 0; i < 16; i++) {
        int j = tid + 256 * i;
        int m = j >> 7, c = j & 127;
        WrT[c * WRT_S + m] = Wr[j];
    }
#pragma unroll
    for (int i = 0; i < 49; i++) {
        int j = tid + 256 * i;
        int m = j >> 5, k = j & 31;
        WsT[k * 392 + m] = Ws[j];
    }
    __syncthreads();

    {
        const int mt = tid >> 5;
        const int nn = (tid & 31) * 4;
        float racc[4][4];
#pragma unroll
        for (int i = 0; i < 4; i++)
#pragma unroll
            for (int j = 0; j < 4; j++) racc[i][j] = 0.f;
#pragma unroll 8
        for (int c = 0; c < 128; c++) {
            float4 av = *(const float4*)&WrT[c * WRT_S + mt * 4];
            float4 bv = *(const float4*)&t1[c * 128 + nn];
            float ar[4] = {av.x, av.y, av.z, av.w};
            float bc[4] = {bv.x, bv.y, bv.z, bv.w};
#pragma unroll
            for (int i = 0; i < 4; i++)
#pragma unroll
                for (int j = 0; j < 4; j++) racc[i][j] += ar[i] * bc[j];
        }
#pragma unroll
        for (int i = 0; i < 4; i++) {
            int m = mt * 4 + i;
            float s = sr[m], bb = br[m];
            float4 v;
            v.x = fmaxf(racc[i][0]*s+bb, 0.f);
            v.y = fmaxf(racc[i][1]*s+bb, 0.f);
            v.z = fmaxf(racc[i][2]*s+bb, 0.f);
            v.w = fmaxf(racc[i][3]*s+bb, 0.f);
            *(float4*)&rshT[m * 128 + nn] = v;
        }
    }
    __syncthreads();

#pragma unroll 1
    for (int it = 0; it < 4; it++) {
        int unit = tid + 256 * it;
        if (unit >= 784) break;
        int mt = unit >> 4, nn = (unit & 15) * 8;
        float acc[8][8];
#pragma unroll
        for (int i = 0; i < 8; i++) {
            float bv = bs[mt * 8 + i];
#pragma unroll
            for (int j = 0; j < 8; j++) acc[i][j] = bv;
        }
#pragma unroll 8
        for (int k = 0; k < 32; k++) {
            float4 a0 = *(const float4*)&WsT[k * 392 + mt * 8];
            float4 a1 = *(const float4*)&WsT[k * 392 + mt * 8 + 4];
            float4 b0 = *(const float4*)&rshT[k * 128 + nn];
            float4 b1 = *(const float4*)&rshT[k * 128 + nn + 4];
            float ar[8] = {a0.x,a0.y,a0.z,a0.w,a1.x,a1.y,a1.z,a1.w};
            float bc[8] = {b0.x,b0.y,b0.z,b0.w,b1.x,b1.y,b1.z,b1.w};
#pragma unroll
            for (int i = 0; i < 8; i++)
#pragma unroll
                for (int j = 0; j < 8; j++) acc[i][j] += ar[i] * bc[j];
        }
        if (n0 + nn < Pn) {
#pragma unroll
            for (int i = 0; i < 8; i++) {
                int m = mt * 8 + i;
                float* wrow = g_w + (b * CSPAN + m) * Pn + n0 + nn;
                float4 v0 = {acc[i][0], acc[i][1], acc[i][2], acc[i][3]};
                float4 v1 = {acc[i][4], acc[i][5], acc[i][6], acc[i][7]};
                *(float4*)&wrow[0] = v0;
                *(float4*)&wrow[4] = v1;
            }
        }
    }
}

// ---------------------------------------------------------------------------
// Kernel 3: involution apply — vertical pixel-pairing (y, y+1) per thread.
// Tap sharing: slot (y+i) serves row y (dy=i, i<7) and row y+1 (dy=i-1, i>=1)
// -> 8 slot-loads feed 14 tap-applies: 1.75x fewer LDS.128 than per-pixel.
// grid (2 half-planes, 8 groups, 16 batch) = 256 blocks, 196/256 threads live.
// Tile: 20 rows x 34 cols x 16 ch, slot stride 20 floats (54.4 KB, 2 CTAs/SM).
// ---------------------------------------------------------------------------
#define APL_SLOT 20
#define APL_R    20
#define APL_SMEM (APL_R * 34 * APL_SLOT * 4)   // 54,400 B

__global__ __launch_bounds__(256, 2) void k_apply() {
    extern __shared__ __align__(16) float xs[];
    const int y0 = blockIdx.x * 14;
    const int g  = blockIdx.y;
    const int b  = blockIdx.z;
    const int tid = threadIdx.x;

    const float* o1 = g_out1 + (b * CMID + g * 16) * Pn;
    for (int j = tid; j < APL_R * 34 * 16; j += 256) {
        int c    = j & 15;
        int slot = j >> 4;
        int xx = slot % 34, yy = slot / 34;
        int gy = y0 + yy - 3, gx = xx - 3;
        float v = 0.f;
        if (gy >= 0 && gy < 28 && gx >= 0 && gx < 28)
            v = o1[c * Pn + gy * 28 + gx];
        xs[slot * APL_SLOT + c] = v;
    }
    __syncthreads();

    if (tid < 196) {
        const int yA = (tid / 28) * 2;          // local output row (even)
        const int xc = tid % 28;
        const int hwA = (y0 + yA) * 28 + xc;
        const int hwB = hwA + 28;
        const float* wbase = g_w + ((size_t)b * CSPAN + (size_t)g * KK) * Pn;

        float accA[16], accB[16];
#pragma unroll
        for (int c = 0; c < 16; c++) { accA[c] = 0.f; accB[c] = 0.f; }

#pragma unroll
        for (int dx = 0; dx < 7; dx++) {
            // preload this dx-column's weights for both rows (14 LDG in flight)
            float wA[7], wB[7];
#pragma unroll
            for (int dy = 0; dy < 7; dy++) {
                const size_t wo = (size_t)(dy * 7 + dx) * Pn;
                wA[dy] = wbase[wo + hwA];
                wB[dy] = wbase[wo + hwB];
            }
#pragma unroll
            for (int i = 0; i < 8; i++) {
                const float* base = &xs[((yA + i) * 34 + xc + dx) * APL_SLOT];
                float4 v0 = *(const float4*)&base[0];
                float4 v1 = *(const float4*)&base[4];
                float4 v2 = *(const float4*)&base[8];
                float4 v3 = *(const float4*)&base[12];
                if (i < 7) {
                    const float w = wA[i];
                    accA[0] += w*v0.x; accA[1] += w*v0.y; accA[2] += w*v0.z; accA[3] += w*v0.w;
                    accA[4] += w*v1.x; accA[5] += w*v1.y; accA[6] += w*v1.z; accA[7] += w*v1.w;
                    accA[8] += w*v2.x; accA[9] += w*v2.y; accA[10]+= w*v2.z; accA[11]+= w*v2.w;
                    accA[12]+= w*v3.x; accA[13]+= w*v3.y; accA[14]+= w*v3.z; accA[15]+= w*v3.w;
                }
                if (i >= 1) {
                    const float w = wB[i - 1];
                    accB[0] += w*v0.x; accB[1] += w*v0.y; accB[2] += w*v0.z; accB[3] += w*v0.w;
                    accB[4] += w*v1.x; accB[5] += w*v1.y; accB[6] += w*v1.z; accB[7] += w*v1.w;
                    accB[8] += w*v2.x; accB[9] += w*v2.y; accB[10]+= w*v2.z; accB[11]+= w*v2.w;
                    accB[12]+= w*v3.x; accB[13]+= w*v3.y; accB[14]+= w*v3.z; accB[15]+= w*v3.w;
                }
            }
        }

        const size_t baseA = (size_t)(b * CMID + g * 16) * Pn + hwA;
#pragma unroll
        for (int c = 0; c < 16; c++) {
            __nv_bfloat16 h, l;
            split2(accA[c], h, l);
            g_o2h[baseA + (size_t)c * Pn] = h;
            g_o2l[baseA + (size_t)c * Pn] = l;
        }
#pragma unroll
        for (int c = 0; c < 16; c++) {
            __nv_bfloat16 h, l;
            split2(accB[c], h, l);
            g_o2h[baseA + 28 + (size_t)c * Pn] = h;
            g_o2l[baseA + 28 + (size_t)c * Pn] = l;
        }
    }
}

// ---------------------------------------------------------------------------
extern "C" void kernel_launch(void* const* d_in, const int* in_sizes, int n_in,
                              void* d_out, int out_size) {
    const float* x  = (const float*)d_in[0];
    const float* W1 = (const float*)d_in[1];
    const float* s1 = (const float*)d_in[2];
    const float* b1 = (const float*)d_in[3];
    const float* Wr = (const float*)d_in[4];
    const float* sr = (const float*)d_in[5];
    const float* br = (const float*)d_in[6];
    const float* Ws = (const float*)d_in[7];
    const float* bs = (const float*)d_in[8];
    const float* W3 = (const float*)d_in[9];
    const float* s3 = (const float*)d_in[10];
    const float* b3 = (const float*)d_in[11];
    float* out = (float*)d_out;

    const int kgen_smem = (16384 + 128 * WRT_S + 4096 + 12544) * 4;
    cudaFuncSetAttribute(k_kgen, cudaFuncAttributeMaxDynamicSharedMemorySize, kgen_smem);
    cudaFuncSetAttribute(k_apply, cudaFuncAttributeMaxDynamicSharedMemorySize, APL_SMEM);
    cudaFuncSetAttribute(k_conv1mm, cudaFuncAttributeMaxDynamicSharedMemorySize, CONV1_SMEM);
    cudaFuncSetAttribute(k_conv3mm, cudaFuncAttributeMaxDynamicSharedMemorySize, CONV3_SMEM);

    // W3 pre-split (independent of everything else)
    k_splitw<<<(CIN * CMID + 255) / 256, 256>>>(W3);
    // conv1: 512 -> 128, BN+ReLU
    k_conv1mm<<<dim3(7, 16), 256, CONV1_SMEM>>>(W1, s1, b1, x);
    // involution kernel generation
    k_kgen<<<dim3(7, 16), 256, kgen_smem>>>(Wr, sr, br, Ws, bs);
    // involution apply (emits split-bf16 o2)
    k_apply<<<dim3(2, NG, BATCH), 256, APL_SMEM>>>();
    // conv3: 128 -> 512, BN + residual
    k_conv3mm<<<dim3(7, 16, 4), 256, CONV3_SMEM>>>(s3, b3, x, out);
}